// round 11
// baseline (speedup 1.0000x reference)
#include <cuda_runtime.h>
#include <cuda_fp16.h>
#include <math.h>
#include <stdint.h>

// Problem constants
#define SS   1024
#define BB   8
#define HH   1024
#define LL   6
#define FFD  4096
#define MR   (SS*BB)

// ---------------------------------------------------------------------------
// Scratch (static device globals; no allocation anywhere)
// ---------------------------------------------------------------------------
__device__ float  g_x  [MR*HH];              // residual stream fp32
__device__ __half g_xh [MR*HH];              // fp16 copy of x
__device__ __half g_qkv[(long)MR*3*HH];      // packed q|k|v per row (fp16)
__device__ __half g_ct [MR*HH];              // ctx (fp16)
__device__ __half g_vt [(long)BB*HH*SS];     // V transposed (B,H,S) fp16
__device__ __half g_sch[(long)BB*SS*SS];     // unnormalized probs exp(s-4) fp16
__device__ float  g_rs [BB*SS];              // row sums (fp32, atomically built)
__device__ __half g_ffh[(long)MR*FFD];       // ff hidden fp16
__device__ __half g_wTh[75497472];           // transposed fp16 weights
__device__ float  g_b3 [LL*3*HH];            // packed qkv bias (bq/32|bk|bv)

// offsets (elements) inside g_wTh
#define QKVT 0L                                  // [L][3][H][H]
#define WOT  (18L*HH*HH)
#define W1T  (WOT + 6L*HH*HH)
#define W2T  (W1T + 6L*HH*FFD)

// ---------------------------------------------------------------------------
// fp16 tensor-core GEMM (mma.sync m16n8k16, fp32 accumulate, ldmatrix frags)
//   acc = A[z] @ B[z]^T ;  epilogue by MODE:
//     0: fp32 out = acc + bias[n] + resid[m][n]      (residual-fused, in-place ok)
//     1: fp16 out = acc + bias
//     2: fp16 out = relu(acc + bias)
//     3: fp16 out = exp(acc-4); atomicAdd per-row sums into rs
//     4: fp16 out = acc / rs[m]
// A: M x K row-major fp16 (lda). B: N x K row-major fp16 (ldb).
// Block tile 128x128x32, 8 warps (32x64), 5-stage cp.async ring. (round-7 core)
// ---------------------------------------------------------------------------
__device__ __forceinline__ void mma16816(float* d, const uint32_t* a,
                                         uint32_t b0, uint32_t b1) {
    asm volatile(
        "mma.sync.aligned.m16n8k16.row.col.f32.f16.f16.f32 "
        "{%0,%1,%2,%3}, {%4,%5,%6,%7}, {%8,%9}, {%0,%1,%2,%3};"
        : "+f"(d[0]), "+f"(d[1]), "+f"(d[2]), "+f"(d[3])
        : "r"(a[0]), "r"(a[1]), "r"(a[2]), "r"(a[3]), "r"(b0), "r"(b1));
}
__device__ __forceinline__ void ldsm4(uint32_t* r, uint32_t addr) {
    asm volatile("ldmatrix.sync.aligned.m8n8.x4.shared.b16 {%0,%1,%2,%3}, [%4];"
                 : "=r"(r[0]), "=r"(r[1]), "=r"(r[2]), "=r"(r[3]) : "r"(addr));
}
__device__ __forceinline__ void cpa16(uint32_t dst, const void* src) {
    asm volatile("cp.async.cg.shared.global [%0], [%1], 16;" :: "r"(dst), "l"(src));
}
#define CP_COMMIT() asm volatile("cp.async.commit_group;" ::: "memory")
#define CP_WAIT(n)  asm volatile("cp.async.wait_group %0;" :: "n"(n) : "memory")

#define LDW     20                        // uint32 words/row (16 data + 4 pad)
#define STAGES  5
#define STG_W   (128 * LDW * 2)           // words per stage (A + B)
#define STG_B   (STG_W * 4u)              // bytes per stage
#define BOFF_B  (128u * LDW * 4u)         // B tile byte offset within stage
#define GEMM_SMEM (STAGES * STG_W * 4)    // 102400 bytes

template<int MODE>
__global__ void __launch_bounds__(256, 2)
gemmh(const __half* __restrict__ A, long sA, int lda,
      const __half* __restrict__ B, long sB, int ldb,
      const float* __restrict__ bias,
      float* rs, long sR,                  // MODE 3: write; MODE 4: read
      const float* resid,                  // MODE 0: residual (may alias Cv)
      void* Cv, long sC, int ldc,
      int K)
{
    extern __shared__ __align__(16) uint32_t sm[];
    const uint32_t sbase = (uint32_t)__cvta_generic_to_shared(sm);

    A += (long)blockIdx.z * sA;
    B += (long)blockIdx.z * sB;
    if (MODE == 3 || MODE == 4) rs += (long)blockIdx.z * sR;
    __half* Ch = (__half*)Cv + (MODE != 0 ? (long)blockIdx.z * sC : 0);
    float*  Cf = (float*) Cv + (MODE == 0 ? (long)blockIdx.z * sC : 0);

    const int bm = blockIdx.y * 128, bn = blockIdx.x * 128;
    const int tid = threadIdx.x;
    const int wid = tid >> 5, lane = tid & 31;
    const int wm = (wid >> 1) * 32, wn = (wid & 1) * 64;
    const int r = lane >> 2, c = lane & 3;

    float acc[2][8][4];
    #pragma unroll
    for (int im = 0; im < 2; im++)
        #pragma unroll
        for (int jn = 0; jn < 8; jn++)
            #pragma unroll
            for (int q = 0; q < 4; q++) acc[im][jn][q] = 0.f;

    // cp.async staging: thread -> row crow, 16B chunks cch, cch+1
    const int crow = tid >> 1;
    const int cch  = (tid & 1) * 2;
    const __half* Arow = A + (long)(bm + crow) * lda;
    const __half* Brow = B + (long)(bn + crow) * ldb;
    const uint32_t adst = sbase + (uint32_t)(crow * LDW + cch * 4) * 4u;
    const uint32_t bdst = adst + BOFF_B;

    auto issue = [&](int t) {
        const uint32_t so = (uint32_t)(t % STAGES) * STG_B;
        const long k0 = (long)t * 32;
        cpa16(adst + so,       Arow + k0 + cch * 8);
        cpa16(adst + so + 16u, Arow + k0 + (cch + 1) * 8);
        cpa16(bdst + so,       Brow + k0 + cch * 8);
        cpa16(bdst + so + 16u, Brow + k0 + (cch + 1) * 8);
        CP_COMMIT();
    };

    // ldmatrix base addresses (validated round-7 lane maps):
    const uint32_t aAddr = sbase
        + (uint32_t)((wm + (lane & 15)) * LDW) * 4u + (uint32_t)(lane >> 4) * 16u;
    const uint32_t bAddr = sbase + BOFF_B
        + (uint32_t)((wn + (lane & 7) + ((lane >> 4) << 3)) * LDW) * 4u
        + (uint32_t)((lane >> 3) & 1) * 16u;

    const int nt = K / 32;
    #pragma unroll
    for (int t = 0; t < STAGES - 1; t++) {
        if (t < nt) issue(t); else CP_COMMIT();
    }

    for (int t = 0; t < nt; t++) {
        CP_WAIT(STAGES - 2);
        __syncthreads();
        if (t + STAGES - 1 < nt) issue(t + STAGES - 1);
        else CP_COMMIT();

        const uint32_t so = (uint32_t)(t % STAGES) * STG_B;
        #pragma unroll
        for (int ks = 0; ks < 2; ks++) {
            const uint32_t ko = so + (uint32_t)ks * 32u;   // ks*8 words
            uint32_t a0[4], a1[4];
            ldsm4(a0, aAddr + ko);
            ldsm4(a1, aAddr + ko + 16u * LDW * 4u);
            #pragma unroll
            for (int jp = 0; jp < 4; jp++) {
                uint32_t b[4];
                ldsm4(b, bAddr + ko + (uint32_t)jp * (16u * LDW * 4u));
                mma16816(acc[0][2*jp    ], a0, b[0], b[1]);
                mma16816(acc[0][2*jp + 1], a0, b[2], b[3]);
                mma16816(acc[1][2*jp    ], a1, b[0], b[1]);
                mma16816(acc[1][2*jp + 1], a1, b[2], b[3]);
            }
        }
    }

    // epilogue
    #pragma unroll
    for (int im = 0; im < 2; im++) {
        const int m = bm + wm + im * 16 + r;
        float rcp0, rcp1;
        if (MODE == 4) { rcp0 = 1.0f / rs[m]; rcp1 = 1.0f / rs[m + 8]; }
        float sum0 = 0.f, sum1 = 0.f;      // MODE 3 row partials
        #pragma unroll
        for (int jn = 0; jn < 8; jn++) {
            int n = bn + wn + jn * 8 + 2 * c;
            float v0 = acc[im][jn][0], v1 = acc[im][jn][1];
            float v2 = acc[im][jn][2], v3 = acc[im][jn][3];
            if (MODE <= 2 && bias) {
                float bb0 = bias[n], bb1 = bias[n + 1];
                v0 += bb0; v1 += bb1; v2 += bb0; v3 += bb1;
            }
            if (MODE == 0) {
                v0 += resid[(long)m * ldc + n];
                v1 += resid[(long)m * ldc + n + 1];
                v2 += resid[(long)(m + 8) * ldc + n];
                v3 += resid[(long)(m + 8) * ldc + n + 1];
            }
            if (MODE == 2) {
                v0 = fmaxf(v0, 0.f); v1 = fmaxf(v1, 0.f);
                v2 = fmaxf(v2, 0.f); v3 = fmaxf(v3, 0.f);
            }
            if (MODE == 3) {
                v0 = expf(v0 - 4.0f); v1 = expf(v1 - 4.0f);
                v2 = expf(v2 - 4.0f); v3 = expf(v3 - 4.0f);
                sum0 += v0 + v1; sum1 += v2 + v3;
            }
            if (MODE == 4) {
                v0 *= rcp0; v1 *= rcp0; v2 *= rcp1; v3 *= rcp1;
            }
            if (MODE != 0) {
                *(__half2*)&Ch[(long)m * ldc + n] = __floats2half2_rn(v0, v1);
                *(__half2*)&Ch[(long)(m + 8) * ldc + n] = __floats2half2_rn(v2, v3);
            } else {
                *(float2*)&Cf[(long)m * ldc + n] = make_float2(v0, v1);
                *(float2*)&Cf[(long)(m + 8) * ldc + n] = make_float2(v2, v3);
            }
        }
        if (MODE == 3) {
            // reduce across the 4 lanes (c = 0..3) sharing rows m, m+8
            #pragma unroll
            for (int o = 1; o <= 2; o <<= 1) {
                sum0 += __shfl_xor_sync(0xffffffffu, sum0, o);
                sum1 += __shfl_xor_sync(0xffffffffu, sum1, o);
            }
            if (c == 0) {
                atomicAdd(&rs[m], sum0);
                atomicAdd(&rs[m + 8], sum1);
            }
        }
    }
}

// ---------------------------------------------------------------------------
// Transposes / packing
// ---------------------------------------------------------------------------
__global__ void transpose_mat_h(const float* __restrict__ src, __half* __restrict__ dst,
                                int R, int C, long zdst, float scale) {
    __shared__ float t[32][33];
    long z = blockIdx.z;
    src += z * (long)R * C;
    dst += z * zdst;
    int r0 = blockIdx.y * 32, c0 = blockIdx.x * 32;
    int x = threadIdx.x, y = threadIdx.y;
    #pragma unroll
    for (int i = 0; i < 32; i += 8)
        t[y + i][x] = src[(long)(r0 + y + i) * C + c0 + x];
    __syncthreads();
    #pragma unroll
    for (int i = 0; i < 32; i += 8)
        dst[(long)(c0 + y + i) * R + r0 + x] = __float2half_rn(t[x][y + i] * scale);
}

__global__ void pack_b3(const float* __restrict__ bq, const float* __restrict__ bk,
                        const float* __restrict__ bv, float* __restrict__ b3) {
    int i = blockIdx.x * 256 + threadIdx.x;
    if (i >= LL * 3 * HH) return;
    int l = i / (3 * HH), j = i % (3 * HH);
    float v;
    if (j < HH)          v = bq[l * HH + j] * (1.0f / 32.0f);
    else if (j < 2 * HH) v = bk[l * HH + j - HH];
    else                 v = bv[l * HH + j - 2 * HH];
    b3[i] = v;
}

// vT[b][h][s] = qkv[(s*B+b)*3H + 2H + h] ; also zeroes g_rs for this batch
__global__ void transpose_v_h(const __half* __restrict__ qkv, __half* __restrict__ vt,
                              float* __restrict__ rs) {
    __shared__ __half t[32][34];
    int b = blockIdx.z;
    int s0 = blockIdx.y * 32, h0 = blockIdx.x * 32;
    int x = threadIdx.x, y = threadIdx.y;
    if (blockIdx.x == 0 && blockIdx.y == 0) {
        int tid = threadIdx.y * 32 + threadIdx.x;      // 0..255
        #pragma unroll
        for (int j = 0; j < 4; j++) rs[b * SS + tid + j * 256] = 0.f;
    }
    #pragma unroll
    for (int i = 0; i < 32; i += 8)
        t[y + i][x] = qkv[((long)(s0 + y + i) * BB + b) * 3 * HH + 2 * HH + h0 + x];
    __syncthreads();
    #pragma unroll
    for (int i = 0; i < 32; i += 8)
        vt[((long)b * HH + h0 + y + i) * SS + s0 + x] = t[x][y + i];
}

// ---------------------------------------------------------------------------
// Embedding + positional encoding (fp32 + fp16)
// ---------------------------------------------------------------------------
__global__ void embed_pe(const int* __restrict__ src,
                         const float* __restrict__ emb,
                         float* __restrict__ x, __half* __restrict__ xh) {
    int row = blockIdx.x;
    int s = row / BB;
    int tok = src[row];
    const float cc = -logf(10000.0f) / (float)HH;
    for (int h = threadIdx.x; h < HH; h += blockDim.x) {
        int i2 = (h >> 1) << 1;
        float div = expf(cc * (float)i2);
        float ang = (float)s * div;
        float pe = (h & 1) ? cosf(ang) : sinf(ang);
        float u = emb[(long)tok * HH + h] * 32.0f + pe;
        x [(long)row * HH + h] = u;
        xh[(long)row * HH + h] = __float2half_rn(u);
    }
}

// ---------------------------------------------------------------------------
// Reductions + LayerNorm
// ---------------------------------------------------------------------------
__device__ __forceinline__ float warpSum(float v) {
    #pragma unroll
    for (int o = 16; o; o >>= 1) v += __shfl_xor_sync(0xffffffffu, v, o);
    return v;
}
__device__ float blockSum(float v) {
    __shared__ float s[8];
    int lane = threadIdx.x & 31, w = threadIdx.x >> 5;
    v = warpSum(v);
    if (!lane) s[w] = v;
    __syncthreads();
    float r;
    if (w == 0) {
        float t = (lane < 8) ? s[lane] : 0.f;
        #pragma unroll
        for (int o = 4; o; o >>= 1) t += __shfl_xor_sync(0xffffffffu, t, o);
        if (!lane) s[0] = t;
    }
    __syncthreads();
    r = s[0];
    __syncthreads();
    return r;
}

// out = LayerNorm(x) * g + b  (in-place on x; optional fp16 copy)
__global__ void ln_only(float* __restrict__ xio,
                        const float* __restrict__ g, const float* __restrict__ b,
                        float* __restrict__ out, __half* __restrict__ outh) {
    long row = blockIdx.x;
    float* px = xio + row * HH;
    int t = threadIdx.x;
    float4 v = *(float4*)&px[t * 4];
    float sum = v.x + v.y + v.z + v.w;
    sum = blockSum(sum);
    float m = sum * (1.0f / HH);
    float ss = (v.x-m)*(v.x-m) + (v.y-m)*(v.y-m) + (v.z-m)*(v.z-m) + (v.w-m)*(v.w-m);
    ss = blockSum(ss);
    float inv = rsqrtf(ss * (1.0f / HH) + 1e-5f);
    float4 gg = *(const float4*)&g[t * 4];
    float4 bb = *(const float4*)&b[t * 4];
    float o0 = (v.x - m) * inv * gg.x + bb.x;
    float o1 = (v.y - m) * inv * gg.y + bb.y;
    float o2 = (v.z - m) * inv * gg.z + bb.z;
    float o3 = (v.w - m) * inv * gg.w + bb.w;
    *(float4*)&out[row * HH + t * 4] = make_float4(o0, o1, o2, o3);
    if (outh) {
        __half2* oh = (__half2*)&outh[row * HH + t * 4];
        oh[0] = __floats2half2_rn(o0, o1);
        oh[1] = __floats2half2_rn(o2, o3);
    }
}

// ---------------------------------------------------------------------------
// Launcher
// ---------------------------------------------------------------------------
extern "C" void kernel_launch(void* const* d_in, const int* in_sizes, int n_in,
                              void* d_out, int out_size)
{
    cudaFuncSetAttribute(gemmh<0>, cudaFuncAttributeMaxDynamicSharedMemorySize, GEMM_SMEM);
    cudaFuncSetAttribute(gemmh<1>, cudaFuncAttributeMaxDynamicSharedMemorySize, GEMM_SMEM);
    cudaFuncSetAttribute(gemmh<2>, cudaFuncAttributeMaxDynamicSharedMemorySize, GEMM_SMEM);
    cudaFuncSetAttribute(gemmh<3>, cudaFuncAttributeMaxDynamicSharedMemorySize, GEMM_SMEM);
    cudaFuncSetAttribute(gemmh<4>, cudaFuncAttributeMaxDynamicSharedMemorySize, GEMM_SMEM);

    float *px, *prs, *pb3;
    __half *pxh, *pqkv, *pct, *pvt, *psch, *pffh, *pwT;
    cudaGetSymbolAddress((void**)&px,   g_x);
    cudaGetSymbolAddress((void**)&pxh,  g_xh);
    cudaGetSymbolAddress((void**)&pqkv, g_qkv);
    cudaGetSymbolAddress((void**)&pct,  g_ct);
    cudaGetSymbolAddress((void**)&pvt,  g_vt);
    cudaGetSymbolAddress((void**)&psch, g_sch);
    cudaGetSymbolAddress((void**)&prs,  g_rs);
    cudaGetSymbolAddress((void**)&pffh, g_ffh);
    cudaGetSymbolAddress((void**)&pwT,  g_wTh);
    cudaGetSymbolAddress((void**)&pb3,  g_b3);

    const int*   src = (const int*)  d_in[0];
    const float* emb = (const float*)d_in[2];
    const float* Wq  = (const float*)d_in[3];
    const float* bq  = (const float*)d_in[4];
    const float* Wk  = (const float*)d_in[5];
    const float* bk  = (const float*)d_in[6];
    const float* Wv  = (const float*)d_in[7];
    const float* bv  = (const float*)d_in[8];
    const float* Wo  = (const float*)d_in[9];
    const float* bo  = (const float*)d_in[10];
    const float* W1  = (const float*)d_in[11];
    const float* b1  = (const float*)d_in[12];
    const float* W2  = (const float*)d_in[13];
    const float* b2  = (const float*)d_in[14];
    const float* g1  = (const float*)d_in[15];
    const float* be1 = (const float*)d_in[16];
    const float* g2  = (const float*)d_in[17];
    const float* be2 = (const float*)d_in[18];
    const float* gf  = (const float*)d_in[19];
    const float* bf  = (const float*)d_in[20];
    float* out = (float*)d_out;

    // one-shot weight transposes -> fp16 [N][K]; Wq scaled by 1/32
    dim3 tb(32, 8);
    transpose_mat_h<<<dim3(HH/32,  HH/32,  LL), tb>>>(Wq, pwT + QKVT,               HH, HH, 3L*HH*HH, 1.0f/32.0f);
    transpose_mat_h<<<dim3(HH/32,  HH/32,  LL), tb>>>(Wk, pwT + QKVT + (long)HH*HH, HH, HH, 3L*HH*HH, 1.0f);
    transpose_mat_h<<<dim3(HH/32,  HH/32,  LL), tb>>>(Wv, pwT + QKVT + 2L*HH*HH,    HH, HH, 3L*HH*HH, 1.0f);
    transpose_mat_h<<<dim3(HH/32,  HH/32,  LL), tb>>>(Wo, pwT + WOT, HH,  HH,  (long)HH*HH,  1.0f);
    transpose_mat_h<<<dim3(FFD/32, HH/32,  LL), tb>>>(W1, pwT + W1T, HH,  FFD, (long)HH*FFD, 1.0f);
    transpose_mat_h<<<dim3(HH/32,  FFD/32, LL), tb>>>(W2, pwT + W2T, FFD, HH,  (long)FFD*HH, 1.0f);
    pack_b3<<<(LL*3*HH + 255)/256, 256>>>(bq, bk, bv, pb3);

    embed_pe<<<MR, 256>>>(src, emb, px, pxh);

    const dim3 gQKV (3*HH / 128, MR / 128, 1);  // (24, 64)
    const dim3 gProj(HH / 128,   MR / 128, 1);  // (8, 64)
    const dim3 gFF1 (FFD / 128,  MR / 128, 1);  // (32, 64)
    const dim3 gAttn(SS / 128,   SS / 128, BB); // (8, 8, 8)
    const dim3 gCtx (HH / 128,   SS / 128, BB); // (8, 8, 8)

    for (int l = 0; l < LL; l++) {
        const __half* qkvT = pwT + QKVT + (long)l * 3 * HH * HH;
        const __half* woT  = pwT + WOT  + (long)l * HH * HH;
        const __half* w1T  = pwT + W1T  + (long)l * HH * FFD;
        const __half* w2T  = pwT + W2T  + (long)l * FFD * HH;
        const float* b3L = pb3 + (long)l * 3 * HH;
        const float* boL = bo + (long)l * HH;
        const float* b1L = b1 + (long)l * FFD;
        const float* b2L = b2 + (long)l * HH;
        const float* g1L = g1 + (long)l * HH;  const float* be1L = be1 + (long)l * HH;
        const float* g2L = g2 + (long)l * HH;  const float* be2L = be2 + (long)l * HH;

        // fused qkv = x @ [Wq/32|Wk|Wv]^T + [bq/32|bk|bv]   (fp16, packed rows)
        gemmh<1><<<gQKV, 256, GEMM_SMEM>>>(pxh, 0, HH, qkvT, 0, HH, b3L,
                                           nullptr, 0, nullptr, pqkv, 0, 3*HH, HH);

        // vT[b][h][s] ; zero row sums
        transpose_v_h<<<dim3(HH/32, SS/32, BB), tb>>>(pqkv, pvt, prs);

        // probs~[b] = exp(Q_b @ K_b^T - 4), row sums accumulated atomically
        gemmh<3><<<gAttn, 256, GEMM_SMEM>>>(pqkv,      3*HH, BB*3*HH,
                                            pqkv + HH, 3*HH, BB*3*HH, nullptr,
                                            prs, SS, nullptr,
                                            psch, (long)SS*SS, SS, HH);

        // ctx[b] = (P~_b @ V_b) / rowsum  -> fp16 (S,B,H)
        gemmh<4><<<gCtx, 256, GEMM_SMEM>>>(psch, (long)SS*SS, SS,
                                           pvt, (long)HH*SS, SS, nullptr,
                                           prs, SS, nullptr,
                                           pct, HH, BB*HH, SS);

        // px = x + ctx Wo + bo (residual fused, in place) ; x = LN(px)
        gemmh<0><<<gProj, 256, GEMM_SMEM>>>(pct, 0, HH, woT, 0, HH, boL,
                                            nullptr, 0, px, px, 0, HH, HH);
        ln_only<<<MR, 256>>>(px, g1L, be1L, px, pxh);

        // ff = relu(x W1 + b1) ; px = x + ff W2 + b2 (fused) ; x = LN(px)
        gemmh<2><<<gFF1, 256, GEMM_SMEM>>>(pxh, 0, HH, w1T, 0, HH, b1L,
                                           nullptr, 0, nullptr, pffh, 0, FFD, HH);
        gemmh<0><<<gProj, 256, GEMM_SMEM>>>(pffh, 0, FFD, w2T, 0, FFD, b2L,
                                            nullptr, 0, px, px, 0, HH, FFD);
        ln_only<<<MR, 256>>>(px, g2L, be2L, px, pxh);
    }

    ln_only<<<MR, 256>>>(px, gf, bf, out, nullptr);
}

// round 13
// speedup vs baseline: 1.0544x; 1.0544x over previous
#include <cuda_runtime.h>
#include <cuda_fp16.h>
#include <math.h>
#include <stdint.h>

// Problem constants
#define SS   1024
#define BB   8
#define HH   1024
#define LL   6
#define FFD  4096
#define MR   (SS*BB)

// ---------------------------------------------------------------------------
// Scratch (static device globals; no allocation anywhere)
// ---------------------------------------------------------------------------
__device__ float  g_x  [MR*HH];              // residual stream fp32
__device__ __half g_xh [MR*HH];              // fp16 copy of x
__device__ __half g_qkv[(long)MR*3*HH];      // packed q|k|v2 per row (fp16)
__device__ __half g_vt [(long)BB*HH*SS];     // V2 transposed (B,H,S) fp16
__device__ __half g_sch[(long)BB*SS*SS];     // unnormalized probs exp(s-4) fp16
__device__ float  g_rs [BB*SS];              // row sums (fp32, atomically built)
__device__ __half g_ffh[(long)MR*FFD];       // ff hidden fp16 (also startup temp)
__device__ __half g_wTh[75497472];           // transposed fp16 weights
__device__ float  g_b3 [LL*3*HH];            // packed qkv bias (bq/32|bk|bv@Wo)

// offsets (elements) inside g_wTh
#define QKVT 0L                                  // [L][3][H][H] (slot3 = WvoT)
#define WOT  (18L*HH*HH)                         // WoT (startup only)
#define W1T  (WOT + 6L*HH*HH)
#define W2T  (W1T + 6L*HH*FFD)

// ---------------------------------------------------------------------------
// fp16 tensor-core GEMM (mma.sync m16n8k16, fp32 accumulate, ldmatrix frags)
//   acc = A[z] @ B[z]^T ;  epilogue by MODE:
//     0: fp32 out = acc + bias[n] + resid[m][n]        (residual fused, in-place)
//     1: fp16 out = acc + bias
//     2: fp16 out = relu(acc + bias)
//     3: fp16 out = exp(acc-4); atomicAdd per-row sums into rs
//     4: fp32 out = acc / rs[m] + bias[n] + resid[m][n] (ctx: softmax-norm+Wo-fold)
// A: M x K row-major fp16 (lda). B: N x K row-major fp16 (ldb).
// Block tile 128x128x32, 8 warps (32x64), 5-stage cp.async ring.
// ---------------------------------------------------------------------------
__device__ __forceinline__ void mma16816(float* d, const uint32_t* a,
                                         uint32_t b0, uint32_t b1) {
    asm volatile(
        "mma.sync.aligned.m16n8k16.row.col.f32.f16.f16.f32 "
        "{%0,%1,%2,%3}, {%4,%5,%6,%7}, {%8,%9}, {%0,%1,%2,%3};"
        : "+f"(d[0]), "+f"(d[1]), "+f"(d[2]), "+f"(d[3])
        : "r"(a[0]), "r"(a[1]), "r"(a[2]), "r"(a[3]), "r"(b0), "r"(b1));
}
__device__ __forceinline__ void ldsm4(uint32_t* r, uint32_t addr) {
    asm volatile("ldmatrix.sync.aligned.m8n8.x4.shared.b16 {%0,%1,%2,%3}, [%4];"
                 : "=r"(r[0]), "=r"(r[1]), "=r"(r[2]), "=r"(r[3]) : "r"(addr));
}
__device__ __forceinline__ void cpa16(uint32_t dst, const void* src) {
    asm volatile("cp.async.cg.shared.global [%0], [%1], 16;" :: "r"(dst), "l"(src));
}
#define CP_COMMIT() asm volatile("cp.async.commit_group;" ::: "memory")
#define CP_WAIT(n)  asm volatile("cp.async.wait_group %0;" :: "n"(n) : "memory")

#define LDW     20                        // uint32 words/row (16 data + 4 pad)
#define STAGES  5
#define STG_W   (128 * LDW * 2)           // words per stage (A + B)
#define STG_B   (STG_W * 4u)              // bytes per stage
#define BOFF_B  (128u * LDW * 4u)         // B tile byte offset within stage
#define GEMM_SMEM (STAGES * STG_W * 4)    // 102400 bytes

template<int MODE>
__global__ void __launch_bounds__(256, 2)
gemmh(const __half* __restrict__ A, long sA, int lda,
      const __half* __restrict__ B, long sB, int ldb,
      const float* __restrict__ bias,
      float* rs, long sR,                  // MODE 3: write; MODE 4: read
      const float* resid,                  // MODE 0/4: residual (may alias Cv)
      void* Cv, long sC, int ldc,
      int K)
{
    extern __shared__ __align__(16) uint32_t sm[];
    const uint32_t sbase = (uint32_t)__cvta_generic_to_shared(sm);

    constexpr bool OUTF = (MODE == 0 || MODE == 4);
    A += (long)blockIdx.z * sA;
    B += (long)blockIdx.z * sB;
    if (MODE == 3 || MODE == 4) rs += (long)blockIdx.z * sR;
    if (OUTF && MODE == 4) resid += (long)blockIdx.z * sC;
    __half* Ch = (__half*)Cv + (!OUTF ? (long)blockIdx.z * sC : 0);
    float*  Cf = (float*) Cv + ( OUTF ? (long)blockIdx.z * sC : 0);

    const int bm = blockIdx.y * 128, bn = blockIdx.x * 128;
    const int tid = threadIdx.x;
    const int wid = tid >> 5, lane = tid & 31;
    const int wm = (wid >> 1) * 32, wn = (wid & 1) * 64;
    const int r = lane >> 2, c = lane & 3;

    float acc[2][8][4];
    #pragma unroll
    for (int im = 0; im < 2; im++)
        #pragma unroll
        for (int jn = 0; jn < 8; jn++)
            #pragma unroll
            for (int q = 0; q < 4; q++) acc[im][jn][q] = 0.f;

    // cp.async staging: thread -> row crow, 16B chunks cch, cch+1
    const int crow = tid >> 1;
    const int cch  = (tid & 1) * 2;
    const __half* Arow = A + (long)(bm + crow) * lda;
    const __half* Brow = B + (long)(bn + crow) * ldb;
    const uint32_t adst = sbase + (uint32_t)(crow * LDW + cch * 4) * 4u;
    const uint32_t bdst = adst + BOFF_B;

    auto issue = [&](int t) {
        const uint32_t so = (uint32_t)(t % STAGES) * STG_B;
        const long k0 = (long)t * 32;
        cpa16(adst + so,       Arow + k0 + cch * 8);
        cpa16(adst + so + 16u, Arow + k0 + (cch + 1) * 8);
        cpa16(bdst + so,       Brow + k0 + cch * 8);
        cpa16(bdst + so + 16u, Brow + k0 + (cch + 1) * 8);
        CP_COMMIT();
    };

    // ldmatrix base addresses (validated round-7 lane maps):
    const uint32_t aAddr = sbase
        + (uint32_t)((wm + (lane & 15)) * LDW) * 4u + (uint32_t)(lane >> 4) * 16u;
    const uint32_t bAddr = sbase + BOFF_B
        + (uint32_t)((wn + (lane & 7) + ((lane >> 4) << 3)) * LDW) * 4u
        + (uint32_t)((lane >> 3) & 1) * 16u;

    const int nt = K / 32;
    #pragma unroll
    for (int t = 0; t < STAGES - 1; t++) {
        if (t < nt) issue(t); else CP_COMMIT();
    }

    for (int t = 0; t < nt; t++) {
        CP_WAIT(STAGES - 2);
        __syncthreads();
        if (t + STAGES - 1 < nt) issue(t + STAGES - 1);
        else CP_COMMIT();

        const uint32_t so = (uint32_t)(t % STAGES) * STG_B;
        #pragma unroll
        for (int ks = 0; ks < 2; ks++) {
            const uint32_t ko = so + (uint32_t)ks * 32u;   // ks*8 words
            uint32_t a0[4], a1[4];
            ldsm4(a0, aAddr + ko);
            ldsm4(a1, aAddr + ko + 16u * LDW * 4u);
            #pragma unroll
            for (int jp = 0; jp < 4; jp++) {
                uint32_t b[4];
                ldsm4(b, bAddr + ko + (uint32_t)jp * (16u * LDW * 4u));
                mma16816(acc[0][2*jp    ], a0, b[0], b[1]);
                mma16816(acc[0][2*jp + 1], a0, b[2], b[3]);
                mma16816(acc[1][2*jp    ], a1, b[0], b[1]);
                mma16816(acc[1][2*jp + 1], a1, b[2], b[3]);
            }
        }
    }

    // epilogue
    #pragma unroll
    for (int im = 0; im < 2; im++) {
        const int m = bm + wm + im * 16 + r;
        float rcp0, rcp1;
        if (MODE == 4) { rcp0 = 1.0f / rs[m]; rcp1 = 1.0f / rs[m + 8]; }
        float sum0 = 0.f, sum1 = 0.f;      // MODE 3 row partials
        #pragma unroll
        for (int jn = 0; jn < 8; jn++) {
            int n = bn + wn + jn * 8 + 2 * c;
            float v0 = acc[im][jn][0], v1 = acc[im][jn][1];
            float v2 = acc[im][jn][2], v3 = acc[im][jn][3];
            if (MODE == 4) {
                v0 *= rcp0; v1 *= rcp0; v2 *= rcp1; v3 *= rcp1;
            }
            if ((MODE <= 2 || MODE == 4) && bias) {
                float bb0 = bias[n], bb1 = bias[n + 1];
                v0 += bb0; v1 += bb1; v2 += bb0; v3 += bb1;
            }
            if (OUTF) {
                v0 += resid[(long)m * ldc + n];
                v1 += resid[(long)m * ldc + n + 1];
                v2 += resid[(long)(m + 8) * ldc + n];
                v3 += resid[(long)(m + 8) * ldc + n + 1];
            }
            if (MODE == 2) {
                v0 = fmaxf(v0, 0.f); v1 = fmaxf(v1, 0.f);
                v2 = fmaxf(v2, 0.f); v3 = fmaxf(v3, 0.f);
            }
            if (MODE == 3) {
                v0 = expf(v0 - 4.0f); v1 = expf(v1 - 4.0f);
                v2 = expf(v2 - 4.0f); v3 = expf(v3 - 4.0f);
                sum0 += v0 + v1; sum1 += v2 + v3;
            }
            if (!OUTF) {
                *(__half2*)&Ch[(long)m * ldc + n] = __floats2half2_rn(v0, v1);
                *(__half2*)&Ch[(long)(m + 8) * ldc + n] = __floats2half2_rn(v2, v3);
            } else {
                *(float2*)&Cf[(long)m * ldc + n] = make_float2(v0, v1);
                *(float2*)&Cf[(long)(m + 8) * ldc + n] = make_float2(v2, v3);
            }
        }
        if (MODE == 3) {
            #pragma unroll
            for (int o = 1; o <= 2; o <<= 1) {
                sum0 += __shfl_xor_sync(0xffffffffu, sum0, o);
                sum1 += __shfl_xor_sync(0xffffffffu, sum1, o);
            }
            if (c == 0) {
                atomicAdd(&rs[m], sum0);
                atomicAdd(&rs[m + 8], sum1);
            }
        }
    }
}

// ---------------------------------------------------------------------------
// Transposes / packing / startup helpers
// ---------------------------------------------------------------------------
__global__ void transpose_mat_h(const float* __restrict__ src, __half* __restrict__ dst,
                                int R, int C, long zdst, float scale) {
    __shared__ float t[32][33];
    long z = blockIdx.z;
    src += z * (long)R * C;
    dst += z * zdst;
    int r0 = blockIdx.y * 32, c0 = blockIdx.x * 32;
    int x = threadIdx.x, y = threadIdx.y;
    #pragma unroll
    for (int i = 0; i < 32; i += 8)
        t[y + i][x] = src[(long)(r0 + y + i) * C + c0 + x];
    __syncthreads();
    #pragma unroll
    for (int i = 0; i < 32; i += 8)
        dst[(long)(c0 + y + i) * R + r0 + x] = __float2half_rn(t[x][y + i] * scale);
}

// plain fp32 -> fp16 copy (grid-stride)
__global__ void f32_to_f16(const float* __restrict__ s, __half* __restrict__ d, long n) {
    for (long i = blockIdx.x * 256L + threadIdx.x; i < n; i += gridDim.x * 256L)
        d[i] = __float2half_rn(s[i]);
}

// b3 segments 0,1: bq/32 | bk
__global__ void pack_b2(const float* __restrict__ bq, const float* __restrict__ bk,
                        float* __restrict__ b3) {
    int i = blockIdx.x * 256 + threadIdx.x;
    if (i >= LL * 2 * HH) return;
    int l = i / (2 * HH), j = i % (2 * HH);
    float v = (j < HH) ? bq[l * HH + j] * (1.0f / 32.0f) : bk[l * HH + j - HH];
    b3[l * 3 * HH + j] = v;
}

// b3 segment 2: (bv @ Wo)[l][j]
__global__ void bvwo_pack(const float* __restrict__ bv, const float* __restrict__ Wo,
                          float* __restrict__ b3) {
    int l = blockIdx.y;
    int j = blockIdx.x * 256 + threadIdx.x;
    const float* w = Wo + (long)l * HH * HH;
    const float* b = bv + l * HH;
    float s = 0.f;
    for (int k = 0; k < HH; k++) s += b[k] * w[(long)k * HH + j];
    b3[l * 3 * HH + 2 * HH + j] = s;
}

// vT[b][h][s] = qkv[(s*B+b)*3H + 2H + h] ; also zeroes g_rs for this batch
__global__ void transpose_v_h(const __half* __restrict__ qkv, __half* __restrict__ vt,
                              float* __restrict__ rs) {
    __shared__ __half t[32][34];
    int b = blockIdx.z;
    int s0 = blockIdx.y * 32, h0 = blockIdx.x * 32;
    int x = threadIdx.x, y = threadIdx.y;
    if (blockIdx.x == 0 && blockIdx.y == 0) {
        int tid = threadIdx.y * 32 + threadIdx.x;
        #pragma unroll
        for (int j = 0; j < 4; j++) rs[b * SS + tid + j * 256] = 0.f;
    }
    #pragma unroll
    for (int i = 0; i < 32; i += 8)
        t[y + i][x] = qkv[((long)(s0 + y + i) * BB + b) * 3 * HH + 2 * HH + h0 + x];
    __syncthreads();
    #pragma unroll
    for (int i = 0; i < 32; i += 8)
        vt[((long)b * HH + h0 + y + i) * SS + s0 + x] = t[x][y + i];
}

// ---------------------------------------------------------------------------
// Embedding + positional encoding (fp32 + fp16)
// ---------------------------------------------------------------------------
__global__ void embed_pe(const int* __restrict__ src,
                         const float* __restrict__ emb,
                         float* __restrict__ x, __half* __restrict__ xh) {
    int row = blockIdx.x;
    int s = row / BB;
    int tok = src[row];
    const float cc = -logf(10000.0f) / (float)HH;
    for (int h = threadIdx.x; h < HH; h += blockDim.x) {
        int i2 = (h >> 1) << 1;
        float div = expf(cc * (float)i2);
        float ang = (float)s * div;
        float pe = (h & 1) ? cosf(ang) : sinf(ang);
        float u = emb[(long)tok * HH + h] * 32.0f + pe;
        x [(long)row * HH + h] = u;
        xh[(long)row * HH + h] = __float2half_rn(u);
    }
}

// ---------------------------------------------------------------------------
// Reductions + LayerNorm
// ---------------------------------------------------------------------------
__device__ __forceinline__ float warpSum(float v) {
    #pragma unroll
    for (int o = 16; o; o >>= 1) v += __shfl_xor_sync(0xffffffffu, v, o);
    return v;
}
__device__ float blockSum(float v) {
    __shared__ float s[8];
    int lane = threadIdx.x & 31, w = threadIdx.x >> 5;
    v = warpSum(v);
    if (!lane) s[w] = v;
    __syncthreads();
    float r;
    if (w == 0) {
        float t = (lane < 8) ? s[lane] : 0.f;
        #pragma unroll
        for (int o = 4; o; o >>= 1) t += __shfl_xor_sync(0xffffffffu, t, o);
        if (!lane) s[0] = t;
    }
    __syncthreads();
    r = s[0];
    __syncthreads();
    return r;
}

// out = LayerNorm(x) * g + b  (in-place on x; optional fp16 copy)
__global__ void ln_only(float* __restrict__ xio,
                        const float* __restrict__ g, const float* __restrict__ b,
                        float* __restrict__ out, __half* __restrict__ outh) {
    long row = blockIdx.x;
    float* px = xio + row * HH;
    int t = threadIdx.x;
    float4 v = *(float4*)&px[t * 4];
    float sum = v.x + v.y + v.z + v.w;
    sum = blockSum(sum);
    float m = sum * (1.0f / HH);
    float ss = (v.x-m)*(v.x-m) + (v.y-m)*(v.y-m) + (v.z-m)*(v.z-m) + (v.w-m)*(v.w-m);
    ss = blockSum(ss);
    float inv = rsqrtf(ss * (1.0f / HH) + 1e-5f);
    float4 gg = *(const float4*)&g[t * 4];
    float4 bb = *(const float4*)&b[t * 4];
    float o0 = (v.x - m) * inv * gg.x + bb.x;
    float o1 = (v.y - m) * inv * gg.y + bb.y;
    float o2 = (v.z - m) * inv * gg.z + bb.z;
    float o3 = (v.w - m) * inv * gg.w + bb.w;
    *(float4*)&out[row * HH + t * 4] = make_float4(o0, o1, o2, o3);
    if (outh) {
        __half2* oh = (__half2*)&outh[row * HH + t * 4];
        oh[0] = __floats2half2_rn(o0, o1);
        oh[1] = __floats2half2_rn(o2, o3);
    }
}

// ---------------------------------------------------------------------------
// Launcher
// ---------------------------------------------------------------------------
extern "C" void kernel_launch(void* const* d_in, const int* in_sizes, int n_in,
                              void* d_out, int out_size)
{
    cudaFuncSetAttribute(gemmh<0>, cudaFuncAttributeMaxDynamicSharedMemorySize, GEMM_SMEM);
    cudaFuncSetAttribute(gemmh<1>, cudaFuncAttributeMaxDynamicSharedMemorySize, GEMM_SMEM);
    cudaFuncSetAttribute(gemmh<2>, cudaFuncAttributeMaxDynamicSharedMemorySize, GEMM_SMEM);
    cudaFuncSetAttribute(gemmh<3>, cudaFuncAttributeMaxDynamicSharedMemorySize, GEMM_SMEM);
    cudaFuncSetAttribute(gemmh<4>, cudaFuncAttributeMaxDynamicSharedMemorySize, GEMM_SMEM);

    float *px, *prs, *pb3;
    __half *pxh, *pqkv, *pvt, *psch, *pffh, *pwT;
    cudaGetSymbolAddress((void**)&px,   g_x);
    cudaGetSymbolAddress((void**)&pxh,  g_xh);
    cudaGetSymbolAddress((void**)&pqkv, g_qkv);
    cudaGetSymbolAddress((void**)&pvt,  g_vt);
    cudaGetSymbolAddress((void**)&psch, g_sch);
    cudaGetSymbolAddress((void**)&prs,  g_rs);
    cudaGetSymbolAddress((void**)&pffh, g_ffh);
    cudaGetSymbolAddress((void**)&pwT,  g_wTh);
    cudaGetSymbolAddress((void**)&pb3,  g_b3);

    const int*   src = (const int*)  d_in[0];
    const float* emb = (const float*)d_in[2];
    const float* Wq  = (const float*)d_in[3];
    const float* bq  = (const float*)d_in[4];
    const float* Wk  = (const float*)d_in[5];
    const float* bk  = (const float*)d_in[6];
    const float* Wv  = (const float*)d_in[7];
    const float* bv  = (const float*)d_in[8];
    const float* Wo  = (const float*)d_in[9];
    const float* bo  = (const float*)d_in[10];
    const float* W1  = (const float*)d_in[11];
    const float* b1  = (const float*)d_in[12];
    const float* W2  = (const float*)d_in[13];
    const float* b2  = (const float*)d_in[14];
    const float* g1  = (const float*)d_in[15];
    const float* be1 = (const float*)d_in[16];
    const float* g2  = (const float*)d_in[17];
    const float* be2 = (const float*)d_in[18];
    const float* gf  = (const float*)d_in[19];
    const float* bf  = (const float*)d_in[20];
    float* out = (float*)d_out;

    // ---- startup: weight prep ----
    dim3 tb(32, 8);
    // Wq/Wk transposed into QKV slots 0,1 (Wq scaled by 1/32)
    transpose_mat_h<<<dim3(HH/32,  HH/32,  LL), tb>>>(Wq, pwT + QKVT,               HH, HH, 3L*HH*HH, 1.0f/32.0f);
    transpose_mat_h<<<dim3(HH/32,  HH/32,  LL), tb>>>(Wk, pwT + QKVT + (long)HH*HH, HH, HH, 3L*HH*HH, 1.0f);
    // WoT (staging for Wvo product), W1T, W2T
    transpose_mat_h<<<dim3(HH/32,  HH/32,  LL), tb>>>(Wo, pwT + WOT, HH,  HH,  (long)HH*HH,  1.0f);
    transpose_mat_h<<<dim3(FFD/32, HH/32,  LL), tb>>>(W1, pwT + W1T, HH,  FFD, (long)HH*FFD, 1.0f);
    transpose_mat_h<<<dim3(HH/32,  FFD/32, LL), tb>>>(W2, pwT + W2T, FFD, HH,  (long)FFD*HH, 1.0f);
    // plain fp16 Wv (temp in pffh), then WvoT = WoT @ Wv^T -> QKV slot 2
    f32_to_f16<<<4096, 256>>>(Wv, pffh, (long)LL*HH*HH);
    gemmh<1><<<dim3(HH/128, HH/128, LL), 256, GEMM_SMEM>>>(
        pwT + WOT, (long)HH*HH, HH, pffh, (long)HH*HH, HH, nullptr,
        nullptr, 0, nullptr, pwT + QKVT + 2L*HH*HH, 3L*HH*HH, HH, HH);
    // biases: bq/32 | bk | bv@Wo
    pack_b2<<<(LL*2*HH + 255)/256, 256>>>(bq, bk, pb3);
    bvwo_pack<<<dim3(HH/256, LL), 256>>>(bv, Wo, pb3);

    embed_pe<<<MR, 256>>>(src, emb, px, pxh);

    const dim3 gQKV (3*HH / 128, MR / 128, 1);  // (24, 64)
    const dim3 gProj(HH / 128,   MR / 128, 1);  // (8, 64)
    const dim3 gFF1 (FFD / 128,  MR / 128, 1);  // (32, 64)
    const dim3 gAttn(SS / 128,   SS / 128, BB); // (8, 8, 8)
    const dim3 gCtx (HH / 128,   SS / 128, BB); // (8, 8, 8)

    for (int l = 0; l < LL; l++) {
        const __half* qkvT = pwT + QKVT + (long)l * 3 * HH * HH;
        const __half* w1T  = pwT + W1T  + (long)l * HH * FFD;
        const __half* w2T  = pwT + W2T  + (long)l * FFD * HH;
        const float* b3L = pb3 + (long)l * 3 * HH;
        const float* boL = bo + (long)l * HH;
        const float* b1L = b1 + (long)l * FFD;
        const float* b2L = b2 + (long)l * HH;
        const float* g1L = g1 + (long)l * HH;  const float* be1L = be1 + (long)l * HH;
        const float* g2L = g2 + (long)l * HH;  const float* be2L = be2 + (long)l * HH;

        // fused qkv2 = x @ [Wq/32 | Wk | Wv@Wo]^T + [bq/32 | bk | bv@Wo]
        gemmh<1><<<gQKV, 256, GEMM_SMEM>>>(pxh, 0, HH, qkvT, 0, HH, b3L,
                                           nullptr, 0, nullptr, pqkv, 0, 3*HH, HH);

        // v2T[b][h][s] ; zero row sums
        transpose_v_h<<<dim3(HH/32, SS/32, BB), tb>>>(pqkv, pvt, prs);

        // probs~[b] = exp(Q_b @ K_b^T - 4), row sums accumulated atomically
        gemmh<3><<<gAttn, 256, GEMM_SMEM>>>(pqkv,      3*HH, BB*3*HH,
                                            pqkv + HH, 3*HH, BB*3*HH, nullptr,
                                            prs, SS, nullptr,
                                            psch, (long)SS*SS, SS, HH);

        // px = x + (P~ @ V2)/rowsum + bo   (attention out, Wo folded, in place)
        gemmh<4><<<gCtx, 256, GEMM_SMEM>>>(psch, (long)SS*SS, SS,
                                           pvt, (long)HH*SS, SS, boL,
                                           prs, SS, px,
                                           px, HH, BB*HH, SS);
        ln_only<<<MR, 256>>>(px, g1L, be1L, px, pxh);

        // ff = relu(x W1 + b1) ; px = x + ff W2 + b2 (fused) ; x = LN(px)
        gemmh<2><<<gFF1, 256, GEMM_SMEM>>>(pxh, 0, HH, w1T, 0, HH, b1L,
                                           nullptr, 0, nullptr, pffh, 0, FFD, HH);
        gemmh<0><<<gProj, 256, GEMM_SMEM>>>(pffh, 0, FFD, w2T, 0, FFD, b2L,
                                            nullptr, 0, px, px, 0, HH, FFD);
        ln_only<<<MR, 256>>>(px, g2L, be2L, px, pxh);
    }

    ln_only<<<MR, 256>>>(px, gf, bf, out, nullptr);
}

// round 14
// speedup vs baseline: 1.0641x; 1.0092x over previous
#include <cuda_runtime.h>
#include <cuda_fp16.h>
#include <math.h>
#include <stdint.h>

// Problem constants
#define SS   1024
#define BB   8
#define HH   1024
#define LL   6
#define FFD  4096
#define MR   (SS*BB)

// ---------------------------------------------------------------------------
// Scratch (static device globals; no allocation anywhere)
// ---------------------------------------------------------------------------
__device__ float  g_x  [MR*HH];              // residual stream fp32
__device__ __half g_xh [MR*HH];              // fp16 copy of x
__device__ __half g_qkv[(long)MR*2*HH];      // packed y|v2 per row (fp16)
__device__ __half g_vt [(long)BB*HH*SS];     // V2 transposed (B,H,S) fp16
__device__ __half g_sch[(long)BB*SS*SS];     // unnorm probs fp16 (+ startup temp)
__device__ float  g_rs [BB*SS];              // row sums (fp32, atomically built)
__device__ float  g_a  [BB*SS];              // a[m] = x[m]·u + c0 (per layer)
__device__ float  g_bs [BB*SS];              // bs[n] = x[n]·w
__device__ __half g_ffh[(long)MR*FFD];       // ff hidden fp16 (also startup temp)
__device__ __half g_wTh[75497472];           // prepared fp16 weights
__device__ float  g_b2 [LL*2*HH];            // qkv bias (0 | bv@Wo)
__device__ float  g_u  [LL*HH];              // (Wq/32)@bk
__device__ float  g_w  [LL*HH];              // Wk@(bq/32)
__device__ float  g_c0 [LL];                 // (bq/32)·bk

// offsets (elements) inside g_wTh
#define QKVT 0L                                  // [L][2][H][H]: Cᵀ | WvoT
#define WOT  (12L*HH*HH)                         // WoT (startup staging)
#define W1T  (WOT + 6L*HH*HH)
#define W2T  (W1T + 6L*HH*FFD)

// ---------------------------------------------------------------------------
// fp16 tensor-core GEMM (mma.sync m16n8k16, fp32 accumulate, ldmatrix frags)
//   acc = A[z] @ B[z]^T ;  epilogue by MODE:
//     0: fp32 out = acc + bias[n] + resid[m][n]        (residual fused, in-place)
//     1: fp16 out = acc + bias
//     2: fp16 out = relu(acc + bias)
//     3: fp16 out = exp(acc + resid[m] + bias[n] - 4); atomicAdd row sums -> rs
//        (resid = a-array, bias = bs-array, both batch-strided by sR)
//     4: fp32 out = acc / rs[m] + bias[n] + resid[m][n] (ctx: norm + Wo-fold)
// A: M x K row-major fp16 (lda). B: N x K row-major fp16 (ldb).
// Block tile 128x128x32, 8 warps (32x64), 5-stage cp.async ring.
// ---------------------------------------------------------------------------
__device__ __forceinline__ void mma16816(float* d, const uint32_t* a,
                                         uint32_t b0, uint32_t b1) {
    asm volatile(
        "mma.sync.aligned.m16n8k16.row.col.f32.f16.f16.f32 "
        "{%0,%1,%2,%3}, {%4,%5,%6,%7}, {%8,%9}, {%0,%1,%2,%3};"
        : "+f"(d[0]), "+f"(d[1]), "+f"(d[2]), "+f"(d[3])
        : "r"(a[0]), "r"(a[1]), "r"(a[2]), "r"(a[3]), "r"(b0), "r"(b1));
}
__device__ __forceinline__ void ldsm4(uint32_t* r, uint32_t addr) {
    asm volatile("ldmatrix.sync.aligned.m8n8.x4.shared.b16 {%0,%1,%2,%3}, [%4];"
                 : "=r"(r[0]), "=r"(r[1]), "=r"(r[2]), "=r"(r[3]) : "r"(addr));
}
__device__ __forceinline__ void cpa16(uint32_t dst, const void* src) {
    asm volatile("cp.async.cg.shared.global [%0], [%1], 16;" :: "r"(dst), "l"(src));
}
#define CP_COMMIT() asm volatile("cp.async.commit_group;" ::: "memory")
#define CP_WAIT(n)  asm volatile("cp.async.wait_group %0;" :: "n"(n) : "memory")

#define LDW     20                        // uint32 words/row (16 data + 4 pad)
#define STAGES  5
#define STG_W   (128 * LDW * 2)           // words per stage (A + B)
#define STG_B   (STG_W * 4u)              // bytes per stage
#define BOFF_B  (128u * LDW * 4u)         // B tile byte offset within stage
#define GEMM_SMEM (STAGES * STG_W * 4)    // 102400 bytes

template<int MODE>
__global__ void __launch_bounds__(256, 2)
gemmh(const __half* __restrict__ A, long sA, int lda,
      const __half* __restrict__ B, long sB, int ldb,
      const float* __restrict__ bias,
      float* rs, long sR,                  // MODE 3: write; MODE 4: read
      const float* resid,                  // MODE 0/4: residual; MODE 3: a-array
      void* Cv, long sC, int ldc,
      int K)
{
    extern __shared__ __align__(16) uint32_t sm[];
    const uint32_t sbase = (uint32_t)__cvta_generic_to_shared(sm);

    constexpr bool OUTF = (MODE == 0 || MODE == 4);
    A += (long)blockIdx.z * sA;
    B += (long)blockIdx.z * sB;
    if (MODE == 3 || MODE == 4) rs += (long)blockIdx.z * sR;
    if (MODE == 4) resid += (long)blockIdx.z * sC;
    if (MODE == 3) { resid += (long)blockIdx.z * sR; bias += (long)blockIdx.z * sR; }
    __half* Ch = (__half*)Cv + (!OUTF ? (long)blockIdx.z * sC : 0);
    float*  Cf = (float*) Cv + ( OUTF ? (long)blockIdx.z * sC : 0);

    const int bm = blockIdx.y * 128, bn = blockIdx.x * 128;
    const int tid = threadIdx.x;
    const int wid = tid >> 5, lane = tid & 31;
    const int wm = (wid >> 1) * 32, wn = (wid & 1) * 64;
    const int r = lane >> 2, c = lane & 3;

    float acc[2][8][4];
    #pragma unroll
    for (int im = 0; im < 2; im++)
        #pragma unroll
        for (int jn = 0; jn < 8; jn++)
            #pragma unroll
            for (int q = 0; q < 4; q++) acc[im][jn][q] = 0.f;

    // cp.async staging: thread -> row crow, 16B chunks cch, cch+1
    const int crow = tid >> 1;
    const int cch  = (tid & 1) * 2;
    const __half* Arow = A + (long)(bm + crow) * lda;
    const __half* Brow = B + (long)(bn + crow) * ldb;
    const uint32_t adst = sbase + (uint32_t)(crow * LDW + cch * 4) * 4u;
    const uint32_t bdst = adst + BOFF_B;

    auto issue = [&](int t) {
        const uint32_t so = (uint32_t)(t % STAGES) * STG_B;
        const long k0 = (long)t * 32;
        cpa16(adst + so,       Arow + k0 + cch * 8);
        cpa16(adst + so + 16u, Arow + k0 + (cch + 1) * 8);
        cpa16(bdst + so,       Brow + k0 + cch * 8);
        cpa16(bdst + so + 16u, Brow + k0 + (cch + 1) * 8);
        CP_COMMIT();
    };

    // ldmatrix base addresses (validated round-7 lane maps):
    const uint32_t aAddr = sbase
        + (uint32_t)((wm + (lane & 15)) * LDW) * 4u + (uint32_t)(lane >> 4) * 16u;
    const uint32_t bAddr = sbase + BOFF_B
        + (uint32_t)((wn + (lane & 7) + ((lane >> 4) << 3)) * LDW) * 4u
        + (uint32_t)((lane >> 3) & 1) * 16u;

    const int nt = K / 32;
    #pragma unroll
    for (int t = 0; t < STAGES - 1; t++) {
        if (t < nt) issue(t); else CP_COMMIT();
    }

    for (int t = 0; t < nt; t++) {
        CP_WAIT(STAGES - 2);
        __syncthreads();
        if (t + STAGES - 1 < nt) issue(t + STAGES - 1);
        else CP_COMMIT();

        const uint32_t so = (uint32_t)(t % STAGES) * STG_B;
        #pragma unroll
        for (int ks = 0; ks < 2; ks++) {
            const uint32_t ko = so + (uint32_t)ks * 32u;   // ks*8 words
            uint32_t a0[4], a1[4];
            ldsm4(a0, aAddr + ko);
            ldsm4(a1, aAddr + ko + 16u * LDW * 4u);
            #pragma unroll
            for (int jp = 0; jp < 4; jp++) {
                uint32_t b[4];
                ldsm4(b, bAddr + ko + (uint32_t)jp * (16u * LDW * 4u));
                mma16816(acc[0][2*jp    ], a0, b[0], b[1]);
                mma16816(acc[0][2*jp + 1], a0, b[2], b[3]);
                mma16816(acc[1][2*jp    ], a1, b[0], b[1]);
                mma16816(acc[1][2*jp + 1], a1, b[2], b[3]);
            }
        }
    }

    // epilogue
    #pragma unroll
    for (int im = 0; im < 2; im++) {
        const int m = bm + wm + im * 16 + r;
        float rcp0, rcp1;
        if (MODE == 4) { rcp0 = 1.0f / rs[m]; rcp1 = 1.0f / rs[m + 8]; }
        float am0, am8;
        if (MODE == 3) { am0 = resid[m] - 4.0f; am8 = resid[m + 8] - 4.0f; }
        float sum0 = 0.f, sum1 = 0.f;      // MODE 3 row partials
        #pragma unroll
        for (int jn = 0; jn < 8; jn++) {
            int n = bn + wn + jn * 8 + 2 * c;
            float v0 = acc[im][jn][0], v1 = acc[im][jn][1];
            float v2 = acc[im][jn][2], v3 = acc[im][jn][3];
            if (MODE == 4) {
                v0 *= rcp0; v1 *= rcp0; v2 *= rcp1; v3 *= rcp1;
            }
            if ((MODE <= 2 || MODE == 4) && bias) {
                float bb0 = bias[n], bb1 = bias[n + 1];
                v0 += bb0; v1 += bb1; v2 += bb0; v3 += bb1;
            }
            if (OUTF) {
                v0 += resid[(long)m * ldc + n];
                v1 += resid[(long)m * ldc + n + 1];
                v2 += resid[(long)(m + 8) * ldc + n];
                v3 += resid[(long)(m + 8) * ldc + n + 1];
            }
            if (MODE == 2) {
                v0 = fmaxf(v0, 0.f); v1 = fmaxf(v1, 0.f);
                v2 = fmaxf(v2, 0.f); v3 = fmaxf(v3, 0.f);
            }
            if (MODE == 3) {
                float bs0 = bias[n], bs1 = bias[n + 1];
                v0 = expf(v0 + am0 + bs0); v1 = expf(v1 + am0 + bs1);
                v2 = expf(v2 + am8 + bs0); v3 = expf(v3 + am8 + bs1);
                sum0 += v0 + v1; sum1 += v2 + v3;
            }
            if (!OUTF) {
                *(__half2*)&Ch[(long)m * ldc + n] = __floats2half2_rn(v0, v1);
                *(__half2*)&Ch[(long)(m + 8) * ldc + n] = __floats2half2_rn(v2, v3);
            } else {
                *(float2*)&Cf[(long)m * ldc + n] = make_float2(v0, v1);
                *(float2*)&Cf[(long)(m + 8) * ldc + n] = make_float2(v2, v3);
            }
        }
        if (MODE == 3) {
            #pragma unroll
            for (int o = 1; o <= 2; o <<= 1) {
                sum0 += __shfl_xor_sync(0xffffffffu, sum0, o);
                sum1 += __shfl_xor_sync(0xffffffffu, sum1, o);
            }
            if (c == 0) {
                atomicAdd(&rs[m], sum0);
                atomicAdd(&rs[m + 8], sum1);
            }
        }
    }
}

// ---------------------------------------------------------------------------
// Transposes / packing / startup helpers
// ---------------------------------------------------------------------------
__global__ void transpose_mat_h(const float* __restrict__ src, __half* __restrict__ dst,
                                int R, int C, long zdst, float scale) {
    __shared__ float t[32][33];
    long z = blockIdx.z;
    src += z * (long)R * C;
    dst += z * zdst;
    int r0 = blockIdx.y * 32, c0 = blockIdx.x * 32;
    int x = threadIdx.x, y = threadIdx.y;
    #pragma unroll
    for (int i = 0; i < 32; i += 8)
        t[y + i][x] = src[(long)(r0 + y + i) * C + c0 + x];
    __syncthreads();
    #pragma unroll
    for (int i = 0; i < 32; i += 8)
        dst[(long)(c0 + y + i) * R + r0 + x] = __float2half_rn(t[x][y + i] * scale);
}

// fp32 -> fp16 copy with scale (grid-stride)
__global__ void f32_to_f16(const float* __restrict__ s, __half* __restrict__ d,
                           long n, float scale) {
    for (long i = blockIdx.x * 256L + threadIdx.x; i < n; i += gridDim.x * 256L)
        d[i] = __float2half_rn(s[i] * scale);
}

// qkv bias: [0 | bv@Wo]
__global__ void pack_bias2(const float* __restrict__ bv, const float* __restrict__ Wo,
                           float* __restrict__ b2) {
    int l = blockIdx.y;
    int j = blockIdx.x * 256 + threadIdx.x;     // 0..2H-1
    float v = 0.f;
    if (j >= HH) {
        int jj = j - HH;
        const float* w = Wo + (long)l * HH * HH;
        const float* b = bv + l * HH;
        for (int k = 0; k < HH; k++) v += b[k] * w[(long)k * HH + jj];
    }
    b2[l * 2 * HH + j] = v;
}

// u[l][h] = dot(Wq[l][h][:], bk[l])/32 ; w[l][h] = dot(Wk[l][h][:], bq[l])/32
__global__ void qk_vecs(const float* __restrict__ Wq, const float* __restrict__ Wk,
                        const float* __restrict__ bq, const float* __restrict__ bk,
                        float* __restrict__ u, float* __restrict__ w) {
    int l = blockIdx.y;
    int h = blockIdx.x * 256 + threadIdx.x;
    const float* wq = Wq + ((long)l * HH + h) * HH;
    const float* wk = Wk + ((long)l * HH + h) * HH;
    const float* pq = bq + l * HH;
    const float* pk = bk + l * HH;
    float su = 0.f, sw = 0.f;
    for (int d = 0; d < HH; d++) { su += wq[d] * pk[d]; sw += wk[d] * pq[d]; }
    u[l * HH + h] = su * (1.0f / 32.0f);
    w[l * HH + h] = sw * (1.0f / 32.0f);
}

__global__ void qk_c0(const float* __restrict__ bq, const float* __restrict__ bk,
                      float* __restrict__ c0) {
    __shared__ float s[8];
    int l = blockIdx.x, t = threadIdx.x;
    float v = 0.f;
    #pragma unroll
    for (int j = 0; j < 4; j++) {
        int d = t + j * 256;
        v += bq[l * HH + d] * bk[l * HH + d];
    }
    #pragma unroll
    for (int o = 16; o; o >>= 1) v += __shfl_xor_sync(0xffffffffu, v, o);
    if ((t & 31) == 0) s[t >> 5] = v;
    __syncthreads();
    if (t == 0) {
        float r = 0.f;
        #pragma unroll
        for (int i = 0; i < 8; i++) r += s[i];
        c0[l] = r * (1.0f / 32.0f);
    }
}

// vT[b][h][s] = qkv[(s*B+b)*2H + H + h] ; also zeroes g_rs for this batch
__global__ void transpose_v_h(const __half* __restrict__ qkv, __half* __restrict__ vt,
                              float* __restrict__ rs) {
    __shared__ __half t[32][34];
    int b = blockIdx.z;
    int s0 = blockIdx.y * 32, h0 = blockIdx.x * 32;
    int x = threadIdx.x, y = threadIdx.y;
    if (blockIdx.x == 0 && blockIdx.y == 0) {
        int tid = threadIdx.y * 32 + threadIdx.x;
        #pragma unroll
        for (int j = 0; j < 4; j++) rs[b * SS + tid + j * 256] = 0.f;
    }
    #pragma unroll
    for (int i = 0; i < 32; i += 8)
        t[y + i][x] = qkv[((long)(s0 + y + i) * BB + b) * 2 * HH + HH + h0 + x];
    __syncthreads();
    #pragma unroll
    for (int i = 0; i < 32; i += 8)
        vt[((long)b * HH + h0 + y + i) * SS + s0 + x] = t[x][y + i];
}

// ---------------------------------------------------------------------------
// Reductions
// ---------------------------------------------------------------------------
__device__ __forceinline__ float warpSum(float v) {
    #pragma unroll
    for (int o = 16; o; o >>= 1) v += __shfl_xor_sync(0xffffffffu, v, o);
    return v;
}
__device__ float blockSum(float v) {
    __shared__ float s[8];
    int lane = threadIdx.x & 31, w = threadIdx.x >> 5;
    v = warpSum(v);
    if (!lane) s[w] = v;
    __syncthreads();
    float r;
    if (w == 0) {
        float t = (lane < 8) ? s[lane] : 0.f;
        #pragma unroll
        for (int o = 4; o; o >>= 1) t += __shfl_xor_sync(0xffffffffu, t, o);
        if (!lane) s[0] = t;
    }
    __syncthreads();
    r = s[0];
    __syncthreads();
    return r;
}

// a[b][s] = xh[row]·u + c0 ; bs[b][s] = xh[row]·w   (row = s*B+b)
__global__ void rowdots(const __half* __restrict__ xh,
                        const float* __restrict__ u, const float* __restrict__ w,
                        const float* __restrict__ c0,
                        float* __restrict__ a, float* __restrict__ bs) {
    long row = blockIdx.x;
    int s = (int)(row / BB), b = (int)(row % BB);
    const __half2* px = (const __half2*)(xh + row * HH);
    int t = threadIdx.x;
    float du = 0.f, dw = 0.f;
    #pragma unroll
    for (int j = 0; j < 2; j++) {
        int i = t + j * 256;
        float2 xv = __half22float2(px[i]);
        float2 uv = *(const float2*)&u[i * 2];
        float2 wv = *(const float2*)&w[i * 2];
        du += xv.x * uv.x + xv.y * uv.y;
        dw += xv.x * wv.x + xv.y * wv.y;
    }
    du = blockSum(du);
    dw = blockSum(dw);
    if (t == 0) { a[b * SS + s] = du + c0[0]; bs[b * SS + s] = dw; }
}

// ---------------------------------------------------------------------------
// Embedding + positional encoding (fp32 + fp16)
// ---------------------------------------------------------------------------
__global__ void embed_pe(const int* __restrict__ src,
                         const float* __restrict__ emb,
                         float* __restrict__ x, __half* __restrict__ xh) {
    int row = blockIdx.x;
    int s = row / BB;
    int tok = src[row];
    const float cc = -logf(10000.0f) / (float)HH;
    for (int h = threadIdx.x; h < HH; h += blockDim.x) {
        int i2 = (h >> 1) << 1;
        float div = expf(cc * (float)i2);
        float ang = (float)s * div;
        float pe = (h & 1) ? cosf(ang) : sinf(ang);
        float u = emb[(long)tok * HH + h] * 32.0f + pe;
        x [(long)row * HH + h] = u;
        xh[(long)row * HH + h] = __float2half_rn(u);
    }
}

// out = LayerNorm(x) * g + b  (in-place on x; optional fp16 copy)
__global__ void ln_only(float* __restrict__ xio,
                        const float* __restrict__ g, const float* __restrict__ b,
                        float* __restrict__ out, __half* __restrict__ outh) {
    long row = blockIdx.x;
    float* px = xio + row * HH;
    int t = threadIdx.x;
    float4 v = *(float4*)&px[t * 4];
    float sum = v.x + v.y + v.z + v.w;
    sum = blockSum(sum);
    float m = sum * (1.0f / HH);
    float ss = (v.x-m)*(v.x-m) + (v.y-m)*(v.y-m) + (v.z-m)*(v.z-m) + (v.w-m)*(v.w-m);
    ss = blockSum(ss);
    float inv = rsqrtf(ss * (1.0f / HH) + 1e-5f);
    float4 gg = *(const float4*)&g[t * 4];
    float4 bb = *(const float4*)&b[t * 4];
    float o0 = (v.x - m) * inv * gg.x + bb.x;
    float o1 = (v.y - m) * inv * gg.y + bb.y;
    float o2 = (v.z - m) * inv * gg.z + bb.z;
    float o3 = (v.w - m) * inv * gg.w + bb.w;
    *(float4*)&out[row * HH + t * 4] = make_float4(o0, o1, o2, o3);
    if (outh) {
        __half2* oh = (__half2*)&outh[row * HH + t * 4];
        oh[0] = __floats2half2_rn(o0, o1);
        oh[1] = __floats2half2_rn(o2, o3);
    }
}

// ---------------------------------------------------------------------------
// Launcher
// ---------------------------------------------------------------------------
extern "C" void kernel_launch(void* const* d_in, const int* in_sizes, int n_in,
                              void* d_out, int out_size)
{
    cudaFuncSetAttribute(gemmh<0>, cudaFuncAttributeMaxDynamicSharedMemorySize, GEMM_SMEM);
    cudaFuncSetAttribute(gemmh<1>, cudaFuncAttributeMaxDynamicSharedMemorySize, GEMM_SMEM);
    cudaFuncSetAttribute(gemmh<2>, cudaFuncAttributeMaxDynamicSharedMemorySize, GEMM_SMEM);
    cudaFuncSetAttribute(gemmh<3>, cudaFuncAttributeMaxDynamicSharedMemorySize, GEMM_SMEM);
    cudaFuncSetAttribute(gemmh<4>, cudaFuncAttributeMaxDynamicSharedMemorySize, GEMM_SMEM);

    float *px, *prs, *pa, *pbs, *pb2, *pu, *pw, *pc0;
    __half *pxh, *pqkv, *pvt, *psch, *pffh, *pwT;
    cudaGetSymbolAddress((void**)&px,   g_x);
    cudaGetSymbolAddress((void**)&pxh,  g_xh);
    cudaGetSymbolAddress((void**)&pqkv, g_qkv);
    cudaGetSymbolAddress((void**)&pvt,  g_vt);
    cudaGetSymbolAddress((void**)&psch, g_sch);
    cudaGetSymbolAddress((void**)&prs,  g_rs);
    cudaGetSymbolAddress((void**)&pa,   g_a);
    cudaGetSymbolAddress((void**)&pbs,  g_bs);
    cudaGetSymbolAddress((void**)&pffh, g_ffh);
    cudaGetSymbolAddress((void**)&pwT,  g_wTh);
    cudaGetSymbolAddress((void**)&pb2,  g_b2);
    cudaGetSymbolAddress((void**)&pu,   g_u);
    cudaGetSymbolAddress((void**)&pw,   g_w);
    cudaGetSymbolAddress((void**)&pc0,  g_c0);

    const int*   src = (const int*)  d_in[0];
    const float* emb = (const float*)d_in[2];
    const float* Wq  = (const float*)d_in[3];
    const float* bq  = (const float*)d_in[4];
    const float* Wk  = (const float*)d_in[5];
    const float* bk  = (const float*)d_in[6];
    const float* Wv  = (const float*)d_in[7];
    const float* bv  = (const float*)d_in[8];
    const float* Wo  = (const float*)d_in[9];
    const float* bo  = (const float*)d_in[10];
    const float* W1  = (const float*)d_in[11];
    const float* b1  = (const float*)d_in[12];
    const float* W2  = (const float*)d_in[13];
    const float* b2  = (const float*)d_in[14];
    const float* g1  = (const float*)d_in[15];
    const float* be1 = (const float*)d_in[16];
    const float* g2  = (const float*)d_in[17];
    const float* be2 = (const float*)d_in[18];
    const float* gf  = (const float*)d_in[19];
    const float* bf  = (const float*)d_in[20];
    float* out = (float*)d_out;

    // ---- startup: weight prep ----
    dim3 tb(32, 8);
    // WoT staging, W1T, W2T
    transpose_mat_h<<<dim3(HH/32,  HH/32,  LL), tb>>>(Wo, pwT + WOT, HH,  HH,  (long)HH*HH,  1.0f);
    transpose_mat_h<<<dim3(FFD/32, HH/32,  LL), tb>>>(W1, pwT + W1T, HH,  FFD, (long)HH*FFD, 1.0f);
    transpose_mat_h<<<dim3(HH/32,  FFD/32, LL), tb>>>(W2, pwT + W2T, FFD, HH,  (long)FFD*HH, 1.0f);
    // fp16 temps: Wq/32 (pffh), Wk (pffh+6M), Wv (psch)
    f32_to_f16<<<4096, 256>>>(Wq, pffh,               (long)LL*HH*HH, 1.0f/32.0f);
    f32_to_f16<<<4096, 256>>>(Wk, pffh + 6L*HH*HH,    (long)LL*HH*HH, 1.0f);
    f32_to_f16<<<4096, 256>>>(Wv, psch,               (long)LL*HH*HH, 1.0f);
    // slot0: Cᵀ[d][h] = Σ_e Wk[d][e]·Wq[h][e]/32
    gemmh<1><<<dim3(HH/128, HH/128, LL), 256, GEMM_SMEM>>>(
        pffh + 6L*HH*HH, (long)HH*HH, HH, pffh, (long)HH*HH, HH, nullptr,
        nullptr, 0, nullptr, pwT + QKVT, 2L*HH*HH, HH, HH);
    // slot1: WvoT[j][i] = Σ_k Wo[k][j]·Wv[i][k]
    gemmh<1><<<dim3(HH/128, HH/128, LL), 256, GEMM_SMEM>>>(
        pwT + WOT, (long)HH*HH, HH, psch, (long)HH*HH, HH, nullptr,
        nullptr, 0, nullptr, pwT + QKVT + (long)HH*HH, 2L*HH*HH, HH, HH);
    // biases + bilinear correction vectors
    pack_bias2<<<dim3(2*HH/256, LL), 256>>>(bv, Wo, pb2);
    qk_vecs<<<dim3(HH/256, LL), 256>>>(Wq, Wk, bq, bk, pu, pw);
    qk_c0<<<LL, 256>>>(bq, bk, pc0);

    embed_pe<<<MR, 256>>>(src, emb, px, pxh);

    const dim3 gQKV (2*HH / 128, MR / 128, 1);  // (16, 64)
    const dim3 gProj(HH / 128,   MR / 128, 1);  // (8, 64)
    const dim3 gFF1 (FFD / 128,  MR / 128, 1);  // (32, 64)
    const dim3 gAttn(SS / 128,   SS / 128, BB); // (8, 8, 8)
    const dim3 gCtx (HH / 128,   SS / 128, BB); // (8, 8, 8)

    for (int l = 0; l < LL; l++) {
        const __half* qkvT = pwT + QKVT + (long)l * 2 * HH * HH;
        const __half* w1T  = pwT + W1T  + (long)l * HH * FFD;
        const __half* w2T  = pwT + W2T  + (long)l * FFD * HH;
        const float* b2L = pb2 + (long)l * 2 * HH;
        const float* boL = bo + (long)l * HH;
        const float* b1L = b1 + (long)l * FFD;
        const float* b2fL = b2 + (long)l * HH;
        const float* g1L = g1 + (long)l * HH;  const float* be1L = be1 + (long)l * HH;
        const float* g2L = g2 + (long)l * HH;  const float* be2L = be2 + (long)l * HH;

        // fused [y | v2] = x @ [Cᵀ | Wv@Wo]ᵀ + [0 | bv@Wo]
        gemmh<1><<<gQKV, 256, GEMM_SMEM>>>(pxh, 0, HH, qkvT, 0, HH, b2L,
                                           nullptr, 0, nullptr, pqkv, 0, 2*HH, HH);

        // rank-1 bias terms a[m], bs[n] from xh
        rowdots<<<MR, 256>>>(pxh, pu + (long)l*HH, pw + (long)l*HH, pc0 + l, pa, pbs);

        // v2T[b][h][s] ; zero row sums
        transpose_v_h<<<dim3(HH/32, SS/32, BB), tb>>>(pqkv, pvt, prs);

        // probs~[b] = exp(y_b @ x_bᵀ + a[m] + bs[n] - 4), row sums atomically
        gemmh<3><<<gAttn, 256, GEMM_SMEM>>>(pqkv, 2*HH, BB*2*HH,
                                            pxh,  HH,   BB*HH, pbs,
                                            prs, SS, pa,
                                            psch, (long)SS*SS, SS, HH);

        // px = x + (P~ @ V2)/rowsum + bo   (attention out, Wo folded, in place)
        gemmh<4><<<gCtx, 256, GEMM_SMEM>>>(psch, (long)SS*SS, SS,
                                           pvt, (long)HH*SS, SS, boL,
                                           prs, SS, px,
                                           px, HH, BB*HH, SS);
        ln_only<<<MR, 256>>>(px, g1L, be1L, px, pxh);

        // ff = relu(x W1 + b1) ; px = x + ff W2 + b2 (fused) ; x = LN(px)
        gemmh<2><<<gFF1, 256, GEMM_SMEM>>>(pxh, 0, HH, w1T, 0, HH, b1L,
                                           nullptr, 0, nullptr, pffh, 0, FFD, HH);
        gemmh<0><<<gProj, 256, GEMM_SMEM>>>(pffh, 0, FFD, w2T, 0, FFD, b2fL,
                                            nullptr, 0, px, px, 0, HH, FFD);
        ln_only<<<MR, 256>>>(px, g2L, be2L, px, pxh);
    }

    ln_only<<<MR, 256>>>(px, gf, bf, out, nullptr);
}

// round 17
// speedup vs baseline: 1.0709x; 1.0064x over previous
#include <cuda_runtime.h>
#include <cuda_fp16.h>
#include <math.h>
#include <stdint.h>

// Problem constants
#define SS   1024
#define BB   8
#define HH   1024
#define LL   6
#define FFD  4096
#define MR   (SS*BB)

// ---------------------------------------------------------------------------
// Scratch (static device globals; no allocation anywhere)
// ---------------------------------------------------------------------------
__device__ float  g_x  [MR*HH];              // residual stream fp32
__device__ __half g_xh [MR*HH];              // fp16 copy of x
__device__ __half g_qkv[(long)MR*2*HH];      // packed y|v2 per row (fp16)
__device__ __half g_vt [(long)BB*HH*SS];     // V2 transposed (B,H,S) fp16
__device__ __half g_sch[(long)BB*SS*SS];     // unnorm probs fp16 (+ startup temp)
__device__ float  g_rs [BB*SS];              // row sums (fp32, atomically built)
__device__ float  g_a  [BB*SS];              // a[m] = x[m]·u + c0 (per layer)
__device__ float  g_bs [BB*SS];              // bs[n] = x[n]·w
__device__ __half g_ffh[(long)MR*FFD];       // ff hidden fp16 (also startup temp)
__device__ __half g_wTh[75497472];           // prepared fp16 weights
__device__ float  g_b2 [LL*2*HH];            // qkv bias (0 | bv@Wo)
__device__ float  g_u  [LL*HH];              // (Wq/32)@bk
__device__ float  g_w  [LL*HH];              // Wk@(bq/32)
__device__ float  g_c0 [LL];                 // (bq/32)·bk

// offsets (elements) inside g_wTh
#define QKVT 0L                                  // [L][2][H][H]: Cᵀ | WvoT
#define WOT  (12L*HH*HH)                         // WoT (startup staging)
#define W1T  (WOT + 6L*HH*HH)
#define W2T  (W1T + 6L*HH*FFD)

// ---------------------------------------------------------------------------
// fp16 tensor-core GEMM (mma.sync m16n8k16, fp32 accumulate, ldmatrix frags)
//   acc = A[z] @ B[z]^T ;  epilogue by MODE:
//     0: fp32 out = acc + bias[n] + resid[m][n]        (residual fused, in-place)
//     1: fp16 out = acc + bias
//     2: fp16 out = relu(acc + bias)
//     3: fp16 out = exp(acc + resid[m] + bias[n] - 4); atomicAdd row sums -> rs
//     4: fp32 out = acc / rs[m] + bias[n] + resid[m][n] (ctx: norm + Wo-fold)
// ---------------------------------------------------------------------------
__device__ __forceinline__ void mma16816(float* d, const uint32_t* a,
                                         uint32_t b0, uint32_t b1) {
    asm volatile(
        "mma.sync.aligned.m16n8k16.row.col.f32.f16.f16.f32 "
        "{%0,%1,%2,%3}, {%4,%5,%6,%7}, {%8,%9}, {%0,%1,%2,%3};"
        : "+f"(d[0]), "+f"(d[1]), "+f"(d[2]), "+f"(d[3])
        : "r"(a[0]), "r"(a[1]), "r"(a[2]), "r"(a[3]), "r"(b0), "r"(b1));
}
__device__ __forceinline__ void ldsm4(uint32_t* r, uint32_t addr) {
    asm volatile("ldmatrix.sync.aligned.m8n8.x4.shared.b16 {%0,%1,%2,%3}, [%4];"
                 : "=r"(r[0]), "=r"(r[1]), "=r"(r[2]), "=r"(r[3]) : "r"(addr));
}
__device__ __forceinline__ void cpa16(uint32_t dst, const void* src) {
    asm volatile("cp.async.cg.shared.global [%0], [%1], 16;" :: "r"(dst), "l"(src));
}
#define CP_COMMIT() asm volatile("cp.async.commit_group;" ::: "memory")
#define CP_WAIT(n)  asm volatile("cp.async.wait_group %0;" :: "n"(n) : "memory")

#define LDW     20
#define STAGES  5
#define STG_W   (128 * LDW * 2)
#define STG_B   (STG_W * 4u)
#define BOFF_B  (128u * LDW * 4u)
#define GEMM_SMEM (STAGES * STG_W * 4)    // 102400 bytes

template<int MODE>
__global__ void __launch_bounds__(256, 2)
gemmh(const __half* __restrict__ A, long sA, int lda,
      const __half* __restrict__ B, long sB, int ldb,
      const float* __restrict__ bias,
      float* rs, long sR,
      const float* resid,
      void* Cv, long sC, int ldc,
      int K)
{
    extern __shared__ __align__(16) uint32_t sm[];
    const uint32_t sbase = (uint32_t)__cvta_generic_to_shared(sm);

    constexpr bool OUTF = (MODE == 0 || MODE == 4);
    A += (long)blockIdx.z * sA;
    B += (long)blockIdx.z * sB;
    if (MODE == 3 || MODE == 4) rs += (long)blockIdx.z * sR;
    if (MODE == 4) resid += (long)blockIdx.z * sC;
    if (MODE == 3) { resid += (long)blockIdx.z * sR; bias += (long)blockIdx.z * sR; }
    __half* Ch = (__half*)Cv + (!OUTF ? (long)blockIdx.z * sC : 0);
    float*  Cf = (float*) Cv + ( OUTF ? (long)blockIdx.z * sC : 0);

    const int bm = blockIdx.y * 128, bn = blockIdx.x * 128;
    const int tid = threadIdx.x;
    const int wid = tid >> 5, lane = tid & 31;
    const int wm = (wid >> 1) * 32, wn = (wid & 1) * 64;
    const int r = lane >> 2, c = lane & 3;

    float acc[2][8][4];
    #pragma unroll
    for (int im = 0; im < 2; im++)
        #pragma unroll
        for (int jn = 0; jn < 8; jn++)
            #pragma unroll
            for (int q = 0; q < 4; q++) acc[im][jn][q] = 0.f;

    const int crow = tid >> 1;
    const int cch  = (tid & 1) * 2;
    const __half* Arow = A + (long)(bm + crow) * lda;
    const __half* Brow = B + (long)(bn + crow) * ldb;
    const uint32_t adst = sbase + (uint32_t)(crow * LDW + cch * 4) * 4u;
    const uint32_t bdst = adst + BOFF_B;

    auto issue = [&](int t) {
        const uint32_t so = (uint32_t)(t % STAGES) * STG_B;
        const long k0 = (long)t * 32;
        cpa16(adst + so,       Arow + k0 + cch * 8);
        cpa16(adst + so + 16u, Arow + k0 + (cch + 1) * 8);
        cpa16(bdst + so,       Brow + k0 + cch * 8);
        cpa16(bdst + so + 16u, Brow + k0 + (cch + 1) * 8);
        CP_COMMIT();
    };

    const uint32_t aAddr = sbase
        + (uint32_t)((wm + (lane & 15)) * LDW) * 4u + (uint32_t)(lane >> 4) * 16u;
    const uint32_t bAddr = sbase + BOFF_B
        + (uint32_t)((wn + (lane & 7) + ((lane >> 4) << 3)) * LDW) * 4u
        + (uint32_t)((lane >> 3) & 1) * 16u;

    const int nt = K / 32;
    #pragma unroll
    for (int t = 0; t < STAGES - 1; t++) {
        if (t < nt) issue(t); else CP_COMMIT();
    }

    for (int t = 0; t < nt; t++) {
        CP_WAIT(STAGES - 2);
        __syncthreads();
        if (t + STAGES - 1 < nt) issue(t + STAGES - 1);
        else CP_COMMIT();

        const uint32_t so = (uint32_t)(t % STAGES) * STG_B;
        #pragma unroll
        for (int ks = 0; ks < 2; ks++) {
            const uint32_t ko = so + (uint32_t)ks * 32u;
            uint32_t a0[4], a1[4];
            ldsm4(a0, aAddr + ko);
            ldsm4(a1, aAddr + ko + 16u * LDW * 4u);
            #pragma unroll
            for (int jp = 0; jp < 4; jp++) {
                uint32_t b[4];
                ldsm4(b, bAddr + ko + (uint32_t)jp * (16u * LDW * 4u));
                mma16816(acc[0][2*jp    ], a0, b[0], b[1]);
                mma16816(acc[0][2*jp + 1], a0, b[2], b[3]);
                mma16816(acc[1][2*jp    ], a1, b[0], b[1]);
                mma16816(acc[1][2*jp + 1], a1, b[2], b[3]);
            }
        }
    }

    #pragma unroll
    for (int im = 0; im < 2; im++) {
        const int m = bm + wm + im * 16 + r;
        float rcp0, rcp1;
        if (MODE == 4) { rcp0 = 1.0f / rs[m]; rcp1 = 1.0f / rs[m + 8]; }
        float am0, am8;
        if (MODE == 3) { am0 = resid[m] - 4.0f; am8 = resid[m + 8] - 4.0f; }
        float sum0 = 0.f, sum1 = 0.f;
        #pragma unroll
        for (int jn = 0; jn < 8; jn++) {
            int n = bn + wn + jn * 8 + 2 * c;
            float v0 = acc[im][jn][0], v1 = acc[im][jn][1];
            float v2 = acc[im][jn][2], v3 = acc[im][jn][3];
            if (MODE == 4) {
                v0 *= rcp0; v1 *= rcp0; v2 *= rcp1; v3 *= rcp1;
            }
            if ((MODE <= 2 || MODE == 4) && bias) {
                float bb0 = bias[n], bb1 = bias[n + 1];
                v0 += bb0; v1 += bb1; v2 += bb0; v3 += bb1;
            }
            if (OUTF) {
                v0 += resid[(long)m * ldc + n];
                v1 += resid[(long)m * ldc + n + 1];
                v2 += resid[(long)(m + 8) * ldc + n];
                v3 += resid[(long)(m + 8) * ldc + n + 1];
            }
            if (MODE == 2) {
                v0 = fmaxf(v0, 0.f); v1 = fmaxf(v1, 0.f);
                v2 = fmaxf(v2, 0.f); v3 = fmaxf(v3, 0.f);
            }
            if (MODE == 3) {
                float bs0 = bias[n], bs1 = bias[n + 1];
                v0 = expf(v0 + am0 + bs0); v1 = expf(v1 + am0 + bs1);
                v2 = expf(v2 + am8 + bs0); v3 = expf(v3 + am8 + bs1);
                sum0 += v0 + v1; sum1 += v2 + v3;
            }
            if (!OUTF) {
                *(__half2*)&Ch[(long)m * ldc + n] = __floats2half2_rn(v0, v1);
                *(__half2*)&Ch[(long)(m + 8) * ldc + n] = __floats2half2_rn(v2, v3);
            } else {
                *(float2*)&Cf[(long)m * ldc + n] = make_float2(v0, v1);
                *(float2*)&Cf[(long)(m + 8) * ldc + n] = make_float2(v2, v3);
            }
        }
        if (MODE == 3) {
            #pragma unroll
            for (int o = 1; o <= 2; o <<= 1) {
                sum0 += __shfl_xor_sync(0xffffffffu, sum0, o);
                sum1 += __shfl_xor_sync(0xffffffffu, sum1, o);
            }
            if (c == 0) {
                atomicAdd(&rs[m], sum0);
                atomicAdd(&rs[m + 8], sum1);
            }
        }
    }
}

// ---------------------------------------------------------------------------
// Transposes / packing / startup helpers
// ---------------------------------------------------------------------------
__global__ void transpose_mat_h(const float* __restrict__ src, __half* __restrict__ dst,
                                int R, int C, long zdst, float scale) {
    __shared__ float t[32][33];
    long z = blockIdx.z;
    src += z * (long)R * C;
    dst += z * zdst;
    int r0 = blockIdx.y * 32, c0 = blockIdx.x * 32;
    int x = threadIdx.x, y = threadIdx.y;
    #pragma unroll
    for (int i = 0; i < 32; i += 8)
        t[y + i][x] = src[(long)(r0 + y + i) * C + c0 + x];
    __syncthreads();
    #pragma unroll
    for (int i = 0; i < 32; i += 8)
        dst[(long)(c0 + y + i) * R + r0 + x] = __float2half_rn(t[x][y + i] * scale);
}

// 3 fp32->fp16 conversions in one kernel (half2 stores)
__global__ void f16copy3(const float* __restrict__ s0, __half* __restrict__ d0, float sc0,
                         const float* __restrict__ s1, __half* __restrict__ d1,
                         const float* __restrict__ s2, __half* __restrict__ d2, long n) {
    long n2 = n >> 1;
    for (long i = blockIdx.x * 256L + threadIdx.x; i < n2; i += gridDim.x * 256L) {
        float2 a = *(const float2*)&s0[i * 2];
        *(__half2*)&d0[i * 2] = __floats2half2_rn(a.x * sc0, a.y * sc0);
        float2 b = *(const float2*)&s1[i * 2];
        *(__half2*)&d1[i * 2] = __floats2half2_rn(b.x, b.y);
        float2 c = *(const float2*)&s2[i * 2];
        *(__half2*)&d2[i * 2] = __floats2half2_rn(c.x, c.y);
    }
}

// qkv bias: [0 | bv@Wo]
__global__ void pack_bias2(const float* __restrict__ bv, const float* __restrict__ Wo,
                           float* __restrict__ b2) {
    int l = blockIdx.y;
    int j = blockIdx.x * 256 + threadIdx.x;
    float v = 0.f;
    if (j >= HH) {
        int jj = j - HH;
        const float* w = Wo + (long)l * HH * HH;
        const float* b = bv + l * HH;
        for (int k = 0; k < HH; k++) v += b[k] * w[(long)k * HH + jj];
    }
    b2[l * 2 * HH + j] = v;
}

__global__ void qk_vecs(const float* __restrict__ Wq, const float* __restrict__ Wk,
                        const float* __restrict__ bq, const float* __restrict__ bk,
                        float* __restrict__ u, float* __restrict__ w) {
    int l = blockIdx.y;
    int h = blockIdx.x * 256 + threadIdx.x;
    const float* wq = Wq + ((long)l * HH + h) * HH;
    const float* wk = Wk + ((long)l * HH + h) * HH;
    const float* pq = bq + l * HH;
    const float* pk = bk + l * HH;
    float su = 0.f, sw = 0.f;
    for (int d = 0; d < HH; d++) { su += wq[d] * pk[d]; sw += wk[d] * pq[d]; }
    u[l * HH + h] = su * (1.0f / 32.0f);
    w[l * HH + h] = sw * (1.0f / 32.0f);
}

__global__ void qk_c0(const float* __restrict__ bq, const float* __restrict__ bk,
                      float* __restrict__ c0) {
    __shared__ float s[8];
    int l = blockIdx.x, t = threadIdx.x;
    float v = 0.f;
    #pragma unroll
    for (int j = 0; j < 4; j++) {
        int d = t + j * 256;
        v += bq[l * HH + d] * bk[l * HH + d];
    }
    #pragma unroll
    for (int o = 16; o; o >>= 1) v += __shfl_xor_sync(0xffffffffu, v, o);
    if ((t & 31) == 0) s[t >> 5] = v;
    __syncthreads();
    if (t == 0) {
        float r = 0.f;
        #pragma unroll
        for (int i = 0; i < 8; i++) r += s[i];
        c0[l] = r * (1.0f / 32.0f);
    }
}

// vT[b][h][s] = qkv[(s*B+b)*2H + H + h]
__global__ void transpose_v_h(const __half* __restrict__ qkv, __half* __restrict__ vt) {
    __shared__ __half t[32][34];
    int b = blockIdx.z;
    int s0 = blockIdx.y * 32, h0 = blockIdx.x * 32;
    int x = threadIdx.x, y = threadIdx.y;
    #pragma unroll
    for (int i = 0; i < 32; i += 8)
        t[y + i][x] = qkv[((long)(s0 + y + i) * BB + b) * 2 * HH + HH + h0 + x];
    __syncthreads();
    #pragma unroll
    for (int i = 0; i < 32; i += 8)
        vt[((long)b * HH + h0 + y + i) * SS + s0 + x] = t[x][y + i];
}

// ---------------------------------------------------------------------------
// Reductions
// ---------------------------------------------------------------------------
__device__ __forceinline__ float warpSum(float v) {
    #pragma unroll
    for (int o = 16; o; o >>= 1) v += __shfl_xor_sync(0xffffffffu, v, o);
    return v;
}
__device__ float blockSum(float v) {
    __shared__ float s[8];
    int lane = threadIdx.x & 31, w = threadIdx.x >> 5;
    v = warpSum(v);
    if (!lane) s[w] = v;
    __syncthreads();
    float r;
    if (w == 0) {
        float t = (lane < 8) ? s[lane] : 0.f;
        #pragma unroll
        for (int o = 4; o; o >>= 1) t += __shfl_xor_sync(0xffffffffu, t, o);
        if (!lane) s[0] = t;
    }
    __syncthreads();
    r = s[0];
    __syncthreads();
    return r;
}

// a[b][s] = xh[row]·u + c0 ; bs[b][s] = xh[row]·w ; rs[b][s] = 0
__global__ void rowdots(const __half* __restrict__ xh,
                        const float* __restrict__ u, const float* __restrict__ w,
                        const float* __restrict__ c0,
                        float* __restrict__ a, float* __restrict__ bs,
                        float* __restrict__ rs) {
    long row = blockIdx.x;
    int s = (int)(row / BB), b = (int)(row % BB);
    const __half2* px = (const __half2*)(xh + row * HH);
    int t = threadIdx.x;
    float du = 0.f, dw = 0.f;
    #pragma unroll
    for (int j = 0; j < 2; j++) {
        int i = t + j * 256;
        float2 xv = __half22float2(px[i]);
        float2 uv = *(const float2*)&u[i * 2];
        float2 wv = *(const float2*)&w[i * 2];
        du += xv.x * uv.x + xv.y * uv.y;
        dw += xv.x * wv.x + xv.y * wv.y;
    }
    du = blockSum(du);
    dw = blockSum(dw);
    if (t == 0) {
        a[b * SS + s] = du + c0[0];
        bs[b * SS + s] = dw;
        rs[b * SS + s] = 0.f;
    }
}

// ---------------------------------------------------------------------------
// Embedding + positional encoding (fp32 + fp16)
// ---------------------------------------------------------------------------
__global__ void embed_pe(const int* __restrict__ src,
                         const float* __restrict__ emb,
                         float* __restrict__ x, __half* __restrict__ xh) {
    int row = blockIdx.x;
    int s = row / BB;
    int tok = src[row];
    const float cc = -logf(10000.0f) / (float)HH;
    for (int h = threadIdx.x; h < HH; h += blockDim.x) {
        int i2 = (h >> 1) << 1;
        float div = expf(cc * (float)i2);
        float ang = (float)s * div;
        float pe = (h & 1) ? cosf(ang) : sinf(ang);
        float u = emb[(long)tok * HH + h] * 32.0f + pe;
        x [(long)row * HH + h] = u;
        xh[(long)row * HH + h] = __float2half_rn(u);
    }
}

// out = LayerNorm(x) * g + b  (in-place on x; optional fp16 copy)
__global__ void ln_only(float* __restrict__ xio,
                        const float* __restrict__ g, const float* __restrict__ b,
                        float* __restrict__ out, __half* __restrict__ outh) {
    long row = blockIdx.x;
    float* px = xio + row * HH;
    int t = threadIdx.x;
    float4 v = *(float4*)&px[t * 4];
    float sum = v.x + v.y + v.z + v.w;
    sum = blockSum(sum);
    float m = sum * (1.0f / HH);
    float ss = (v.x-m)*(v.x-m) + (v.y-m)*(v.y-m) + (v.z-m)*(v.z-m) + (v.w-m)*(v.w-m);
    ss = blockSum(ss);
    float inv = rsqrtf(ss * (1.0f / HH) + 1e-5f);
    float4 gg = *(const float4*)&g[t * 4];
    float4 bb = *(const float4*)&b[t * 4];
    float o0 = (v.x - m) * inv * gg.x + bb.x;
    float o1 = (v.y - m) * inv * gg.y + bb.y;
    float o2 = (v.z - m) * inv * gg.z + bb.z;
    float o3 = (v.w - m) * inv * gg.w + bb.w;
    *(float4*)&out[row * HH + t * 4] = make_float4(o0, o1, o2, o3);
    if (outh) {
        __half2* oh = (__half2*)&outh[row * HH + t * 4];
        oh[0] = __floats2half2_rn(o0, o1);
        oh[1] = __floats2half2_rn(o2, o3);
    }
}

// ---------------------------------------------------------------------------
// Launcher (dual-stream graph: s0 = capture/default, s1 = side stream)
// ---------------------------------------------------------------------------
extern "C" void kernel_launch(void* const* d_in, const int* in_sizes, int n_in,
                              void* d_out, int out_size)
{
    // lazily-created side stream + events (host handles only; identical work
    // is enqueued on every call, so graph capture is deterministic)
    static cudaStream_t s1 = nullptr;
    static cudaEvent_t evA = nullptr, evB = nullptr, evL = nullptr,
                       evR = nullptr, evQ = nullptr, evT = nullptr;
    if (!s1) {
        cudaStreamCreateWithFlags(&s1, cudaStreamNonBlocking);
        cudaEventCreateWithFlags(&evA, cudaEventDisableTiming);
        cudaEventCreateWithFlags(&evB, cudaEventDisableTiming);
        cudaEventCreateWithFlags(&evL, cudaEventDisableTiming);
        cudaEventCreateWithFlags(&evR, cudaEventDisableTiming);
        cudaEventCreateWithFlags(&evQ, cudaEventDisableTiming);
        cudaEventCreateWithFlags(&evT, cudaEventDisableTiming);
    }

    cudaFuncSetAttribute(gemmh<0>, cudaFuncAttributeMaxDynamicSharedMemorySize, GEMM_SMEM);
    cudaFuncSetAttribute(gemmh<1>, cudaFuncAttributeMaxDynamicSharedMemorySize, GEMM_SMEM);
    cudaFuncSetAttribute(gemmh<2>, cudaFuncAttributeMaxDynamicSharedMemorySize, GEMM_SMEM);
    cudaFuncSetAttribute(gemmh<3>, cudaFuncAttributeMaxDynamicSharedMemorySize, GEMM_SMEM);
    cudaFuncSetAttribute(gemmh<4>, cudaFuncAttributeMaxDynamicSharedMemorySize, GEMM_SMEM);

    float *px, *prs, *pa, *pbs, *pb2, *pu, *pw, *pc0;
    __half *pxh, *pqkv, *pvt, *psch, *pffh, *pwT;
    cudaGetSymbolAddress((void**)&px,   g_x);
    cudaGetSymbolAddress((void**)&pxh,  g_xh);
    cudaGetSymbolAddress((void**)&pqkv, g_qkv);
    cudaGetSymbolAddress((void**)&pvt,  g_vt);
    cudaGetSymbolAddress((void**)&psch, g_sch);
    cudaGetSymbolAddress((void**)&prs,  g_rs);
    cudaGetSymbolAddress((void**)&pa,   g_a);
    cudaGetSymbolAddress((void**)&pbs,  g_bs);
    cudaGetSymbolAddress((void**)&pffh, g_ffh);
    cudaGetSymbolAddress((void**)&pwT,  g_wTh);
    cudaGetSymbolAddress((void**)&pb2,  g_b2);
    cudaGetSymbolAddress((void**)&pu,   g_u);
    cudaGetSymbolAddress((void**)&pw,   g_w);
    cudaGetSymbolAddress((void**)&pc0,  g_c0);

    const int*   src = (const int*)  d_in[0];
    const float* emb = (const float*)d_in[2];
    const float* Wq  = (const float*)d_in[3];
    const float* bq  = (const float*)d_in[4];
    const float* Wk  = (const float*)d_in[5];
    const float* bk  = (const float*)d_in[6];
    const float* Wv  = (const float*)d_in[7];
    const float* bv  = (const float*)d_in[8];
    const float* Wo  = (const float*)d_in[9];
    const float* bo  = (const float*)d_in[10];
    const float* W1  = (const float*)d_in[11];
    const float* b1  = (const float*)d_in[12];
    const float* W2  = (const float*)d_in[13];
    const float* b2  = (const float*)d_in[14];
    const float* g1  = (const float*)d_in[15];
    const float* be1 = (const float*)d_in[16];
    const float* g2  = (const float*)d_in[17];
    const float* be2 = (const float*)d_in[18];
    const float* gf  = (const float*)d_in[19];
    const float* bf  = (const float*)d_in[20];
    float* out = (float*)d_out;

    dim3 tb(32, 8);

    // ---- fork s1 for startup prep ----
    cudaEventRecord(evA, 0);
    cudaStreamWaitEvent(s1, evA, 0);

    // s1: WoT staging, fp16 weight temps, prep GEMMs, bias/qk vectors
    transpose_mat_h<<<dim3(HH/32, HH/32, LL), tb, 0, s1>>>(Wo, pwT + WOT, HH, HH,
                                                           (long)HH*HH, 1.0f);
    f16copy3<<<4096, 256, 0, s1>>>(Wq, pffh, 1.0f/32.0f,
                                   Wk, pffh + 6L*HH*HH,
                                   Wv, psch, (long)LL*HH*HH);
    // slot0: Cᵀ[d][h] = Σ_e Wk[d][e]·Wq[h][e]/32
    gemmh<1><<<dim3(HH/128, HH/128, LL), 256, GEMM_SMEM, s1>>>(
        pffh + 6L*HH*HH, (long)HH*HH, HH, pffh, (long)HH*HH, HH, nullptr,
        nullptr, 0, nullptr, pwT + QKVT, 2L*HH*HH, HH, HH);
    // slot1: WvoT[j][i] = Σ_k Wo[k][j]·Wv[i][k]
    gemmh<1><<<dim3(HH/128, HH/128, LL), 256, GEMM_SMEM, s1>>>(
        pwT + WOT, (long)HH*HH, HH, psch, (long)HH*HH, HH, nullptr,
        nullptr, 0, nullptr, pwT + QKVT + (long)HH*HH, 2L*HH*HH, HH, HH);
    pack_bias2<<<dim3(2*HH/256, LL), 256, 0, s1>>>(bv, Wo, pb2);
    qk_vecs<<<dim3(HH/256, LL), 256, 0, s1>>>(Wq, Wk, bq, bk, pu, pw);
    qk_c0<<<LL, 256, 0, s1>>>(bq, bk, pc0);
    cudaEventRecord(evB, s1);

    // s0 (concurrent): embedding + big FF transposes
    embed_pe<<<MR, 256>>>(src, emb, px, pxh);
    transpose_mat_h<<<dim3(FFD/32, HH/32,  LL), tb>>>(W1, pwT + W1T, HH,  FFD,
                                                      (long)HH*FFD, 1.0f);
    transpose_mat_h<<<dim3(HH/32,  FFD/32, LL), tb>>>(W2, pwT + W2T, FFD, HH,
                                                      (long)FFD*HH, 1.0f);
    cudaStreamWaitEvent(0, evB, 0);          // join prep
    cudaEventRecord(evL, 0);                 // xh ready marker for layer 0

    const dim3 gQKV (2*HH / 128, MR / 128, 1);
    const dim3 gProj(HH / 128,   MR / 128, 1);
    const dim3 gFF1 (FFD / 128,  MR / 128, 1);
    const dim3 gAttn(SS / 128,   SS / 128, BB);
    const dim3 gCtx (HH / 128,   SS / 128, BB);

    for (int l = 0; l < LL; l++) {
        const __half* qkvT = pwT + QKVT + (long)l * 2 * HH * HH;
        const __half* w1T  = pwT + W1T  + (long)l * HH * FFD;
        const __half* w2T  = pwT + W2T  + (long)l * FFD * HH;
        const float* b2L = pb2 + (long)l * 2 * HH;
        const float* boL = bo + (long)l * HH;
        const float* b1L = b1 + (long)l * FFD;
        const float* b2fL = b2 + (long)l * HH;
        const float* g1L = g1 + (long)l * HH;  const float* be1L = be1 + (long)l * HH;
        const float* g2L = g2 + (long)l * HH;  const float* be2L = be2 + (long)l * HH;

        // s1: rowdots (a, bs, rs=0) concurrent with qkv GEMM
        cudaStreamWaitEvent(s1, evL, 0);
        rowdots<<<MR, 256, 0, s1>>>(pxh, pu + (long)l*HH, pw + (long)l*HH,
                                    pc0 + l, pa, pbs, prs);
        cudaEventRecord(evR, s1);

        // s0: fused [y | v2] = x @ [Cᵀ | Wv@Wo]ᵀ + [0 | bv@Wo]
        gemmh<1><<<gQKV, 256, GEMM_SMEM>>>(pxh, 0, HH, qkvT, 0, HH, b2L,
                                           nullptr, 0, nullptr, pqkv, 0, 2*HH, HH);
        cudaEventRecord(evQ, 0);

        // s1: v2 transpose concurrent with scores GEMM
        cudaStreamWaitEvent(s1, evQ, 0);
        transpose_v_h<<<dim3(HH/32, SS/32, BB), tb, 0, s1>>>(pqkv, pvt);
        cudaEventRecord(evT, s1);

        // s0: probs~ = exp(y @ xᵀ + a[m] + bs[n] - 4), row sums atomically
        cudaStreamWaitEvent(0, evR, 0);
        gemmh<3><<<gAttn, 256, GEMM_SMEM>>>(pqkv, 2*HH, BB*2*HH,
                                            pxh,  HH,   BB*HH, pbs,
                                            prs, SS, pa,
                                            psch, (long)SS*SS, SS, HH);

        // s0: px = x + (P~ @ V2)/rowsum + bo (in place)
        cudaStreamWaitEvent(0, evT, 0);
        gemmh<4><<<gCtx, 256, GEMM_SMEM>>>(psch, (long)SS*SS, SS,
                                           pvt, (long)HH*SS, SS, boL,
                                           prs, SS, px,
                                           px, HH, BB*HH, SS);
        ln_only<<<MR, 256>>>(px, g1L, be1L, px, pxh);

        // s0: ff = relu(x W1 + b1) ; px = x + ff W2 + b2 ; x = LN(px)
        gemmh<2><<<gFF1, 256, GEMM_SMEM>>>(pxh, 0, HH, w1T, 0, HH, b1L,
                                           nullptr, 0, nullptr, pffh, 0, FFD, HH);
        gemmh<0><<<gProj, 256, GEMM_SMEM>>>(pffh, 0, FFD, w2T, 0, FFD, b2fL,
                                            nullptr, 0, px, px, 0, HH, FFD);
        ln_only<<<MR, 256>>>(px, g2L, be2L, px, pxh);
        cudaEventRecord(evL, 0);
    }

    ln_only<<<MR, 256>>>(px, gf, bf, out, nullptr);
}